// round 1
// baseline (speedup 1.0000x reference)
#include <cuda_runtime.h>
#include <cstdint>

#define C_CAPS 64
#define S_DIM 2048
#define H_DIM 512
#define M_ROWS (C_CAPS * S_DIM)   // 131072
#define NCHUNK 8
#define CHUNK_S (S_DIM / NCHUNK)  // 256

typedef unsigned long long ull;

// -------- device scratch (allocation-free rule: __device__ globals) --------
__device__ float g_e[(size_t)M_ROWS * H_DIM];        // raw linear output (pre-squash), 256 MB
__device__ float g_norms[4 * M_ROWS];                // per-column-tile partial row sum of squares
__device__ float g_b[M_ROWS];                        // routing logits b_ij
__device__ float g_c[C_CAPS * H_DIM];                // c_i between iterations
__device__ float g_Mp[C_CAPS * NCHUNK];              // chunk softmax max
__device__ float g_Zp[C_CAPS * NCHUNK];              // chunk softmax denom (sum exp)
__device__ float g_Vp[C_CAPS * NCHUNK * H_DIM];      // chunk weighted-sum numerators

// ============================================================================
// Kernel 1: e' = x @ W^T + bias, plus per-row sum-of-squares partials.
// 128x128 tile, BK=8, 256 threads, 8x8 per thread, packed f32x2 FMA.
// ============================================================================
__global__ void __launch_bounds__(256, 2) gemm_kernel(
    const float* __restrict__ x,
    const float* __restrict__ W,
    const float* __restrict__ bias)
{
    __shared__ __align__(16) float As[8][136];
    __shared__ __align__(16) float Bs[8][136];

    const int t  = threadIdx.x;
    const int tx = t & 15;        // 0..15 -> column group
    const int ty = t >> 4;        // 0..15 -> row group
    const int bm = blockIdx.y;
    const int bn = blockIdx.x;

    const int srow = t >> 1;
    const int sk   = (t & 1) * 4;

    const float* aptr = x + ((size_t)bm * 128 + srow) * 512 + sk;
    const float* bptr = W + ((size_t)bn * 128 + srow) * 512 + sk;

    ull acc[8][4];
#pragma unroll
    for (int i = 0; i < 8; i++)
#pragma unroll
        for (int p = 0; p < 4; p++) acc[i][p] = 0ULL;

    float4 pa = *(const float4*)aptr;
    float4 pb = *(const float4*)bptr;

    for (int kt = 0; kt < 64; ++kt) {
        As[sk + 0][srow] = pa.x; As[sk + 1][srow] = pa.y;
        As[sk + 2][srow] = pa.z; As[sk + 3][srow] = pa.w;
        Bs[sk + 0][srow] = pb.x; Bs[sk + 1][srow] = pb.y;
        Bs[sk + 2][srow] = pb.z; Bs[sk + 3][srow] = pb.w;
        __syncthreads();

        if (kt < 63) {
            pa = *(const float4*)(aptr + (kt + 1) * 8);
            pb = *(const float4*)(bptr + (kt + 1) * 8);
        }

#pragma unroll
        for (int k = 0; k < 8; k++) {
            ull b2[4];
#pragma unroll
            for (int p = 0; p < 4; p++)
                b2[p] = *(const ull*)&Bs[k][tx * 2 + 32 * p];

            float4 a0 = *(const float4*)&As[k][ty * 8];
            float4 a1 = *(const float4*)&As[k][ty * 8 + 4];
            float av[8] = {a0.x, a0.y, a0.z, a0.w, a1.x, a1.y, a1.z, a1.w};

#pragma unroll
            for (int i = 0; i < 8; i++) {
                unsigned au = __float_as_uint(av[i]);
                ull a2;
                asm("mov.b64 %0, {%1,%2};" : "=l"(a2) : "r"(au), "r"(au));
#pragma unroll
                for (int p = 0; p < 4; p++)
                    asm("fma.rn.f32x2 %0, %1, %2, %0;"
                        : "+l"(acc[i][p]) : "l"(a2), "l"(b2[p]));
            }
        }
        __syncthreads();
    }

    // Epilogue: add bias, store e', reduce per-row sum of squares across tx.
    float bx[4], by[4];
#pragma unroll
    for (int p = 0; p < 4; p++) {
        int col = bn * 128 + tx * 2 + 32 * p;
        float2 bb = *(const float2*)&bias[col];
        bx[p] = bb.x; by[p] = bb.y;
    }

#pragma unroll
    for (int i = 0; i < 8; i++) {
        int grow = bm * 128 + ty * 8 + i;
        float rs = 0.f;
#pragma unroll
        for (int p = 0; p < 4; p++) {
            int col = bn * 128 + tx * 2 + 32 * p;
            float v0 = __uint_as_float((unsigned)(acc[i][p])) + bx[p];
            float v1 = __uint_as_float((unsigned)(acc[i][p] >> 32)) + by[p];
            *(float2*)&g_e[(size_t)grow * 512 + col] = make_float2(v0, v1);
            rs += v0 * v0 + v1 * v1;
        }
        // reduce across the 16 tx lanes (width-16 segments of the warp)
        rs += __shfl_down_sync(0xffffffffu, rs, 8, 16);
        rs += __shfl_down_sync(0xffffffffu, rs, 4, 16);
        rs += __shfl_down_sync(0xffffffffu, rs, 2, 16);
        rs += __shfl_down_sync(0xffffffffu, rs, 1, 16);
        if (tx == 0)
            g_norms[(size_t)bn * M_ROWS + grow] = rs;
    }
}

// ============================================================================
// Kernel 2: one fused routing pass.
//   b_new_s = b_s + squash(e'_s) . c_prev       (c_prev = 0 on pass 0)
//   chunk-local online softmax over b_new, weighted sum of squash(e'_s)
//   writes per-chunk (M, Z, V[512]) partials; b updated in place.
// grid = (NCHUNK, C_CAPS), 256 threads.
// ============================================================================
__global__ void __launch_bounds__(256) routing_pass()
{
    const int c     = blockIdx.y;
    const int chunk = blockIdx.x;
    const int t     = threadIdx.x;
    const int warp  = t >> 5;
    const int lane  = t & 31;

    __shared__ float csm[512];
    __shared__ float bsh[CHUNK_S];
    __shared__ float scl[CHUNK_S];
    __shared__ float wsh[CHUNK_S];
    __shared__ float red[8];
    __shared__ float Mtot, Ztot;

    csm[t]       = g_c[c * 512 + t];
    csm[t + 256] = g_c[c * 512 + t + 256];
    __syncthreads();

    const int s0 = chunk * CHUNK_S;

    // --- sub-pass 1: logit dots + squash scale + b update ---
    for (int r = 0; r < 32; ++r) {
        int sl  = warp * 32 + r;
        int row = c * S_DIM + s0 + sl;
        const float4* ep = (const float4*)(g_e + (size_t)row * 512);
        float dot = 0.f;
#pragma unroll
        for (int j = 0; j < 4; j++) {
            float4 v  = ep[lane + 32 * j];
            float4 cv = *(const float4*)&csm[4 * (lane + 32 * j)];
            dot += v.x * cv.x + v.y * cv.y + v.z * cv.z + v.w * cv.w;
        }
#pragma unroll
        for (int off = 16; off > 0; off >>= 1)
            dot += __shfl_xor_sync(0xffffffffu, dot, off);
        if (lane == 0) {
            float sq = g_norms[row] + g_norms[M_ROWS + row]
                     + g_norms[2 * M_ROWS + row] + g_norms[3 * M_ROWS + row];
            float scale = (sq / (1.f + sq)) * rsqrtf(sq + 1e-7f);
            float bn = g_b[row] + scale * dot;
            g_b[row] = bn;
            bsh[sl] = bn;
            scl[sl] = scale;
        }
    }
    __syncthreads();

    // --- block max over bsh ---
    float m = bsh[t];
#pragma unroll
    for (int off = 16; off > 0; off >>= 1)
        m = fmaxf(m, __shfl_xor_sync(0xffffffffu, m, off));
    if (lane == 0) red[warp] = m;
    __syncthreads();
    if (t == 0) {
        float mm = red[0];
#pragma unroll
        for (int k = 1; k < 8; k++) mm = fmaxf(mm, red[k]);
        Mtot = mm;
    }
    __syncthreads();
    float M = Mtot;

    // --- weights + Z ---
    float eb = expf(bsh[t] - M);
    wsh[t] = eb * scl[t];            // fold squash scale into the weight
    float z = eb;
#pragma unroll
    for (int off = 16; off > 0; off >>= 1)
        z += __shfl_xor_sync(0xffffffffu, z, off);
    if (lane == 0) red[warp] = z;
    __syncthreads();
    if (t == 0) {
        float zz = 0.f;
#pragma unroll
        for (int k = 0; k < 8; k++) zz += red[k];
        Ztot = zz;
    }
    __syncthreads();

    // --- sub-pass 2: weighted vector sum (chunk is L2-resident now) ---
    float ax = 0.f, ay = 0.f;
    const float* ebase = g_e + ((size_t)(c * S_DIM + s0)) * 512 + 2 * t;
#pragma unroll 8
    for (int sl = 0; sl < CHUNK_S; ++sl) {
        float w = wsh[sl];
        float2 v = *(const float2*)(ebase + (size_t)sl * 512);
        ax += w * v.x;
        ay += w * v.y;
    }
    int pc = c * NCHUNK + chunk;
    *(float2*)&g_Vp[(size_t)pc * 512 + 2 * t] = make_float2(ax, ay);
    if (t == 0) { g_Mp[pc] = M; g_Zp[pc] = Ztot; }
}

// ============================================================================
// Kernel 3: combine chunk partials -> c_new = squash(sum_s d_s e_s)
// grid = C_CAPS, 256 threads.
// ============================================================================
__global__ void __launch_bounds__(256) combine_kernel(float* __restrict__ out)
{
    const int c = blockIdx.x;
    const int t = threadIdx.x;
    const int warp = t >> 5, lane = t & 31;

    __shared__ float sk[NCHUNK];
    __shared__ float red[8];
    __shared__ float Zs, Sq;

    if (t == 0) {
        float M = g_Mp[c * NCHUNK];
#pragma unroll
        for (int k = 1; k < NCHUNK; k++) M = fmaxf(M, g_Mp[c * NCHUNK + k]);
        float Z = 0.f;
#pragma unroll
        for (int k = 0; k < NCHUNK; k++) {
            float e = expf(g_Mp[c * NCHUNK + k] - M);
            sk[k] = e;
            Z += g_Zp[c * NCHUNK + k] * e;
        }
        Zs = Z;
    }
    __syncthreads();

    float w0 = 0.f, w1 = 0.f;
#pragma unroll
    for (int k = 0; k < NCHUNK; k++) {
        float e = sk[k];
        float2 v = *(const float2*)&g_Vp[((size_t)(c * NCHUNK + k)) * 512 + 2 * t];
        w0 += e * v.x;
        w1 += e * v.y;
    }
    float invZ = 1.f / Zs;
    w0 *= invZ; w1 *= invZ;

    float s2 = w0 * w0 + w1 * w1;
#pragma unroll
    for (int off = 16; off > 0; off >>= 1)
        s2 += __shfl_xor_sync(0xffffffffu, s2, off);
    if (lane == 0) red[warp] = s2;
    __syncthreads();
    if (t == 0) {
        float ss = 0.f;
#pragma unroll
        for (int k = 0; k < 8; k++) ss += red[k];
        Sq = ss;
    }
    __syncthreads();

    float sq = Sq;
    float scale = (sq / (1.f + sq)) * rsqrtf(sq + 1e-7f);
    out[c * 512 + 2 * t]     = scale * w0;
    out[c * 512 + 2 * t + 1] = scale * w1;
}

// ============================================================================
extern "C" void kernel_launch(void* const* d_in, const int* in_sizes, int n_in,
                              void* d_out, int out_size)
{
    const float* x    = (const float*)d_in[0];
    const float* W    = (const float*)d_in[1];
    const float* bias = (const float*)d_in[2];
    float* out = (float*)d_out;

    void* pb = nullptr; cudaGetSymbolAddress(&pb, g_b);
    void* pc = nullptr; cudaGetSymbolAddress(&pc, g_c);
    cudaMemsetAsync(pb, 0, (size_t)M_ROWS * sizeof(float));
    cudaMemsetAsync(pc, 0, (size_t)C_CAPS * H_DIM * sizeof(float));

    dim3 gg(4, 1024);   // bn fastest-varying -> 4 consecutive CTAs share the x row-block (L2 reuse)
    gemm_kernel<<<gg, 256>>>(x, W, bias);

    for (int it = 0; it < 3; ++it) {
        routing_pass<<<dim3(NCHUNK, C_CAPS), 256>>>();
        combine_kernel<<<C_CAPS, 256>>>(it == 2 ? out : (float*)pc);
    }
}

// round 3
// speedup vs baseline: 1.4631x; 1.4631x over previous
#include <cuda_runtime.h>
#include <cuda_bf16.h>
#include <cstdint>

#define C_CAPS 64
#define S_DIM 2048
#define H_DIM 512
#define M_ROWS (C_CAPS * S_DIM)   // 131072
#define NCHUNK 16
#define CHUNK_S (S_DIM / NCHUNK)  // 128
#define RSTG 16
#define NSTG (CHUNK_S / RSTG)     // 8

// ---------------- device scratch ----------------
__device__ __align__(128) float g_e[(size_t)M_ROWS * H_DIM];   // 256 MB
__device__ float g_norms[4 * M_ROWS];                          // per-bn partial row sumsq
__device__ float g_b[M_ROWS];
__device__ float g_c[C_CAPS * H_DIM];
__device__ float g_Mp[C_CAPS * NCHUNK];
__device__ float g_Zp[C_CAPS * NCHUNK];
__device__ float g_Vp[(size_t)C_CAPS * NCHUNK * H_DIM];

// ---------------- helpers ----------------
__device__ __forceinline__ uint32_t smem_u32(const void* p) {
    uint32_t a;
    asm("{ .reg .u64 t; cvta.to.shared.u64 t, %1; cvt.u32.u64 %0, t; }" : "=r"(a) : "l"(p));
    return a;
}

__device__ __forceinline__ void ldsm4(uint32_t* r, uint32_t addr) {
    asm volatile("ldmatrix.sync.aligned.m8n8.x4.shared.b16 {%0,%1,%2,%3}, [%4];"
        : "=r"(r[0]), "=r"(r[1]), "=r"(r[2]), "=r"(r[3]) : "r"(addr));
}

__device__ __forceinline__ void mma16816(float* d, const uint32_t* a, const uint32_t* b) {
    asm volatile("mma.sync.aligned.m16n8k16.row.col.f32.bf16.bf16.f32 "
        "{%0,%1,%2,%3}, {%4,%5,%6,%7}, {%8,%9}, {%0,%1,%2,%3};"
        : "+f"(d[0]), "+f"(d[1]), "+f"(d[2]), "+f"(d[3])
        : "r"(a[0]), "r"(a[1]), "r"(a[2]), "r"(a[3]), "r"(b[0]), "r"(b[1]));
}

__device__ __forceinline__ void sts128(uint32_t addr, uint4 v) {
    asm volatile("st.shared.v4.b32 [%0], {%1,%2,%3,%4};"
        :: "r"(addr), "r"(v.x), "r"(v.y), "r"(v.z), "r"(v.w) : "memory");
}

// split fp32 pair -> packed bf16 hi pair + lo pair
__device__ __forceinline__ void split2(float x, float y, uint32_t& h, uint32_t& l) {
    __nv_bfloat16 hx = __float2bfloat16_rn(x);
    __nv_bfloat16 hy = __float2bfloat16_rn(y);
    __nv_bfloat16 lx = __float2bfloat16_rn(x - __bfloat162float(hx));
    __nv_bfloat16 ly = __float2bfloat16_rn(y - __bfloat162float(hy));
    h = (uint32_t)__bfloat16_as_ushort(hy) << 16 | __bfloat16_as_ushort(hx);
    l = (uint32_t)__bfloat16_as_ushort(ly) << 16 | __bfloat16_as_ushort(lx);
}
__device__ __forceinline__ void split_chunk(const float4& a, const float4& b, uint4& hi, uint4& lo) {
    split2(a.x, a.y, hi.x, lo.x);
    split2(a.z, a.w, hi.y, lo.y);
    split2(b.x, b.y, hi.z, lo.z);
    split2(b.z, b.w, hi.w, lo.w);
}

// swizzled byte offset inside an 8KB [128 x 32] bf16 tile; kc = 16B chunk (0..3)
__device__ __forceinline__ uint32_t tswz(uint32_t row, uint32_t kc) {
    return row * 64u + ((kc ^ ((row >> 1) & 3u)) << 4);
}

// ============================================================================
// GEMM: g_e[M,512] = x[M,512] @ W[512,512]^T + bias, bf16 3-product split,
// tile 128x128, BK=32, 8 warps (warp tile 32x64), mma.sync m16n8k16.
// Dynamic smem: 2 stages x (Ahi 8K | Alo 8K | Bhi 8K | Blo 8K) + 512B norms.
// ============================================================================
#define GSM_STAGE 32768
#define GSM_TOTAL (2 * GSM_STAGE + 512)

__global__ void __launch_bounds__(256, 1) gemm_mma(
    const float* __restrict__ x,
    const float* __restrict__ W,
    const float* __restrict__ bias)
{
    extern __shared__ __align__(1024) char smem[];
    const uint32_t sb = smem_u32(smem);

    const int t = threadIdx.x;
    const int l = t & 31;
    const int wid = t >> 5;
    const int wm = wid & 3;          // 4 m-strips of 32 rows
    const int wn = wid >> 2;         // 2 n-strips of 64 cols
    const int bn = blockIdx.x;       // 0..3
    const int mtile = blockIdx.y;    // 0..1023

    // ---- per-thread global load chunks: c = t and t+256; chunk -> (row, kc)
    const int c0row = t >> 2, ckc = t & 3;
    const float* ag0 = x + ((size_t)mtile * 128 + c0row) * 512 + ckc * 8;
    const float* ag1 = x + ((size_t)mtile * 128 + c0row + 64) * 512 + ckc * 8;
    const float* bg0 = W + ((size_t)bn * 128 + c0row) * 512 + ckc * 8;
    const float* bg1 = W + ((size_t)bn * 128 + c0row + 64) * 512 + ckc * 8;
    const uint32_t so0 = tswz(c0row, ckc);
    const uint32_t so1 = tswz(c0row + 64, ckc);

    // ---- ldmatrix per-lane addresses (byte offsets within a tile region)
    uint32_t aoffA[2][2], aoffB[4][2];
#pragma unroll
    for (int mt = 0; mt < 2; mt++)
#pragma unroll
        for (int ks = 0; ks < 2; ks++) {
            uint32_t m = wm * 32 + mt * 16 + ((l >> 3) & 1) * 8 + (l & 7);
            uint32_t kc = ks * 2 + (l >> 4);
            aoffA[mt][ks] = tswz(m, kc);
        }
#pragma unroll
    for (int nt2 = 0; nt2 < 4; nt2++)
#pragma unroll
        for (int ks = 0; ks < 2; ks++) {
            uint32_t n = wn * 64 + nt2 * 16 + ((l >> 4) & 1) * 8 + (l & 7);
            uint32_t kc = ks * 2 + ((l >> 3) & 1);
            aoffB[nt2][ks] = tswz(n, kc);
        }

    float acc[2][8][4];
#pragma unroll
    for (int mt = 0; mt < 2; mt++)
#pragma unroll
        for (int nt = 0; nt < 8; nt++)
#pragma unroll
            for (int k = 0; k < 4; k++) acc[mt][nt][k] = 0.f;

    // ---- prefetch stage 0
    float4 pa[2][2], pb[2][2];
    pa[0][0] = *(const float4*)(ag0);     pa[0][1] = *(const float4*)(ag0 + 4);
    pa[1][0] = *(const float4*)(ag1);     pa[1][1] = *(const float4*)(ag1 + 4);
    pb[0][0] = *(const float4*)(bg0);     pb[0][1] = *(const float4*)(bg0 + 4);
    pb[1][0] = *(const float4*)(bg1);     pb[1][1] = *(const float4*)(bg1 + 4);

    for (int kt = 0; kt < 16; kt++) {
        const uint32_t stg = sb + (kt & 1) * GSM_STAGE;

        // store converted chunks: A hi/lo, B hi/lo
        {
            uint4 hi, lo;
            split_chunk(pa[0][0], pa[0][1], hi, lo);
            sts128(stg + so0, hi);            sts128(stg + 8192 + so0, lo);
            split_chunk(pa[1][0], pa[1][1], hi, lo);
            sts128(stg + so1, hi);            sts128(stg + 8192 + so1, lo);
            split_chunk(pb[0][0], pb[0][1], hi, lo);
            sts128(stg + 16384 + so0, hi);    sts128(stg + 24576 + so0, lo);
            split_chunk(pb[1][0], pb[1][1], hi, lo);
            sts128(stg + 16384 + so1, hi);    sts128(stg + 24576 + so1, lo);
        }
        __syncthreads();

        if (kt < 15) {
            int ko = (kt + 1) * 32;
            pa[0][0] = *(const float4*)(ag0 + ko); pa[0][1] = *(const float4*)(ag0 + ko + 4);
            pa[1][0] = *(const float4*)(ag1 + ko); pa[1][1] = *(const float4*)(ag1 + ko + 4);
            pb[0][0] = *(const float4*)(bg0 + ko); pb[0][1] = *(const float4*)(bg0 + ko + 4);
            pb[1][0] = *(const float4*)(bg1 + ko); pb[1][1] = *(const float4*)(bg1 + ko + 4);
        }

#pragma unroll
        for (int ks = 0; ks < 2; ks++) {
            uint32_t ah[2][4], al[2][4], bh[4][4], bl[4][4];
#pragma unroll
            for (int mt = 0; mt < 2; mt++) {
                ldsm4(ah[mt], stg + aoffA[mt][ks]);
                ldsm4(al[mt], stg + 8192 + aoffA[mt][ks]);
            }
#pragma unroll
            for (int nt2 = 0; nt2 < 4; nt2++) {
                ldsm4(bh[nt2], stg + 16384 + aoffB[nt2][ks]);
                ldsm4(bl[nt2], stg + 24576 + aoffB[nt2][ks]);
            }
#pragma unroll
            for (int mt = 0; mt < 2; mt++)
#pragma unroll
                for (int nt = 0; nt < 8; nt++) {
                    const uint32_t* Bh = &bh[nt >> 1][(nt & 1) * 2];
                    const uint32_t* Bl = &bl[nt >> 1][(nt & 1) * 2];
                    mma16816(acc[mt][nt], ah[mt], Bh);
                    mma16816(acc[mt][nt], ah[mt], Bl);
                    mma16816(acc[mt][nt], al[mt], Bh);
                }
        }
        __syncthreads();
    }

    // ---- epilogue: bias add, store, row-norm partials ----
    float* norm_sm = (float*)(smem + 2 * GSM_STAGE);
    if (t < 128) norm_sm[t] = 0.f;
    __syncthreads();

    float2 bias2[8];
#pragma unroll
    for (int nt = 0; nt < 8; nt++)
        bias2[nt] = *(const float2*)&bias[bn * 128 + wn * 64 + nt * 8 + (l & 3) * 2];

#pragma unroll
    for (int mt = 0; mt < 2; mt++)
#pragma unroll
        for (int half = 0; half < 2; half++) {
            int r = wm * 32 + mt * 16 + (l >> 2) + half * 8;
            float* erow = g_e + ((size_t)mtile * 128 + r) * 512 + bn * 128 + wn * 64;
            float ss = 0.f;
#pragma unroll
            for (int nt = 0; nt < 8; nt++) {
                float vx = acc[mt][nt][half * 2]     + bias2[nt].x;
                float vy = acc[mt][nt][half * 2 + 1] + bias2[nt].y;
                ss += vx * vx + vy * vy;
                *(float2*)&erow[nt * 8 + (l & 3) * 2] = make_float2(vx, vy);
            }
            ss += __shfl_xor_sync(0xffffffffu, ss, 1);
            ss += __shfl_xor_sync(0xffffffffu, ss, 2);
            if ((l & 3) == 0) atomicAdd(&norm_sm[r], ss);
        }
    __syncthreads();
    if (t < 128)
        g_norms[(size_t)bn * M_ROWS + (size_t)mtile * 128 + t] = norm_sm[t];
}

// ============================================================================
// Routing pass: single sweep with online softmax (chunk partials).
// ============================================================================
__global__ void __launch_bounds__(256) routing_pass() {
    const int c = blockIdx.y, chunk = blockIdx.x;
    const int t = threadIdx.x, wid = t >> 5, lane = t & 31;

    __shared__ float tile[RSTG][512];
    __shared__ float csm[512];
    __shared__ float bst[RSTG], sst[RSTG], wst[RSTG];
    __shared__ float runMs, Zsh, fsh;

    csm[t] = g_c[c * 512 + t];
    csm[t + 256] = g_c[c * 512 + t + 256];
    if (t == 0) { runMs = -1e30f; Zsh = 0.f; }

    const size_t rowbase = (size_t)c * S_DIM + (size_t)chunk * CHUNK_S;
    float ax = 0.f, ay = 0.f;
    __syncthreads();

    for (int st = 0; st < NSTG; st++) {
        const float4* gsrc = (const float4*)(g_e + (rowbase + st * RSTG) * 512);
        float4* td = (float4*)&tile[0][0];
#pragma unroll
        for (int i = 0; i < 8; i++) td[t + 256 * i] = gsrc[t + 256 * i];
        __syncthreads();

#pragma unroll
        for (int rr = 0; rr < 2; rr++) {
            int rl = wid * 2 + rr;
            const float4* tr = (const float4*)&tile[rl][0];
            float dot = 0.f;
#pragma unroll
            for (int j = 0; j < 4; j++) {
                float4 v = tr[lane + 32 * j];
                float4 cv = *(const float4*)&csm[(lane + 32 * j) * 4];
                dot += v.x * cv.x + v.y * cv.y + v.z * cv.z + v.w * cv.w;
            }
#pragma unroll
            for (int off = 16; off > 0; off >>= 1)
                dot += __shfl_xor_sync(0xffffffffu, dot, off);
            if (lane == 0) {
                size_t row = rowbase + st * RSTG + rl;
                float sq = g_norms[row] + g_norms[M_ROWS + row]
                         + g_norms[2 * M_ROWS + row] + g_norms[3 * M_ROWS + row];
                float scale = (sq / (1.f + sq)) * rsqrtf(sq + 1e-7f);
                float bnv = g_b[row] + scale * dot;
                g_b[row] = bnv;
                bst[rl] = bnv;
                sst[rl] = scale;
            }
        }
        __syncthreads();

        if (t < 32) {
            float v = (lane < RSTG) ? bst[lane] : -1e30f;
            float m = v;
#pragma unroll
            for (int off = 16; off > 0; off >>= 1)
                m = fmaxf(m, __shfl_xor_sync(0xffffffffu, m, off));
            float rm = runMs;
            float nm = fmaxf(rm, m);
            float w = __expf(v - nm);
            float zst = w;
#pragma unroll
            for (int off = 16; off > 0; off >>= 1)
                zst += __shfl_xor_sync(0xffffffffu, zst, off);
            if (lane < RSTG) wst[lane] = w * sst[lane];
            if (lane == 0) {
                float f = __expf(rm - nm);
                fsh = f;
                Zsh = Zsh * f + zst;
                runMs = nm;
            }
        }
        __syncthreads();

        float f = fsh;
        ax *= f; ay *= f;
#pragma unroll
        for (int r = 0; r < RSTG; r++) {
            float w = wst[r];
            float2 v = *(const float2*)&tile[r][2 * t];
            ax += w * v.x;
            ay += w * v.y;
        }
        __syncthreads();
    }

    int pc = c * NCHUNK + chunk;
    *(float2*)&g_Vp[(size_t)pc * 512 + 2 * t] = make_float2(ax, ay);
    if (t == 0) { g_Mp[pc] = runMs; g_Zp[pc] = Zsh; }
}

// ============================================================================
// Combine chunk partials -> c = squash(sum d_s e_s)
// ============================================================================
__global__ void __launch_bounds__(256) combine_kernel(float* __restrict__ out) {
    const int c = blockIdx.x, t = threadIdx.x;
    const int wid = t >> 5, lane = t & 31;

    __shared__ float sk[NCHUNK];
    __shared__ float red[8];
    __shared__ float Zs, Sq;

    if (t == 0) {
        float M = g_Mp[c * NCHUNK];
#pragma unroll
        for (int k = 1; k < NCHUNK; k++) M = fmaxf(M, g_Mp[c * NCHUNK + k]);
        float Z = 0.f;
#pragma unroll
        for (int k = 0; k < NCHUNK; k++) {
            float e = __expf(g_Mp[c * NCHUNK + k] - M);
            sk[k] = e;
            Z += g_Zp[c * NCHUNK + k] * e;
        }
        Zs = Z;
    }
    __syncthreads();

    float w0 = 0.f, w1 = 0.f;
#pragma unroll
    for (int k = 0; k < NCHUNK; k++) {
        float e = sk[k];
        float2 v = *(const float2*)&g_Vp[((size_t)(c * NCHUNK + k)) * 512 + 2 * t];
        w0 += e * v.x;
        w1 += e * v.y;
    }
    float invZ = 1.f / Zs;
    w0 *= invZ; w1 *= invZ;

    float s2 = w0 * w0 + w1 * w1;
#pragma unroll
    for (int off = 16; off > 0; off >>= 1)
        s2 += __shfl_xor_sync(0xffffffffu, s2, off);
    if (lane == 0) red[wid] = s2;
    __syncthreads();
    if (t == 0) {
        float ss = 0.f;
#pragma unroll
        for (int k = 0; k < 8; k++) ss += red[k];
        Sq = ss;
    }
    __syncthreads();

    float sq = Sq;
    float scale = (sq / (1.f + sq)) * rsqrtf(sq + 1e-7f);
    out[c * 512 + 2 * t]     = scale * w0;
    out[c * 512 + 2 * t + 1] = scale * w1;
}

// ============================================================================
extern "C" void kernel_launch(void* const* d_in, const int* in_sizes, int n_in,
                              void* d_out, int out_size) {
    const float* x    = (const float*)d_in[0];
    const float* W    = (const float*)d_in[1];
    const float* bias = (const float*)d_in[2];
    float* out = (float*)d_out;

    void* pb = nullptr; cudaGetSymbolAddress(&pb, g_b);
    void* pc = nullptr; cudaGetSymbolAddress(&pc, g_c);
    cudaMemsetAsync(pb, 0, (size_t)M_ROWS * sizeof(float));
    cudaMemsetAsync(pc, 0, (size_t)C_CAPS * H_DIM * sizeof(float));

    static bool attr_done = false;
    if (!attr_done) {
        cudaFuncSetAttribute(gemm_mma, cudaFuncAttributeMaxDynamicSharedMemorySize, GSM_TOTAL);
        attr_done = true;
    }
    gemm_mma<<<dim3(4, 1024), 256, GSM_TOTAL>>>(x, W, bias);

    for (int it = 0; it < 3; ++it) {
        routing_pass<<<dim3(NCHUNK, C_CAPS), 256>>>();
        combine_kernel<<<C_CAPS, 256>>>(it == 2 ? out : (float*)pc);
    }
}

// round 4
// speedup vs baseline: 1.5292x; 1.0452x over previous
#include <cuda_runtime.h>
#include <cuda_bf16.h>
#include <cstdint>

#define C_CAPS 64
#define S_DIM 2048
#define H_DIM 512
#define M_ROWS (C_CAPS * S_DIM)   // 131072
#define NCHUNK 16
#define CHUNK_S (S_DIM / NCHUNK)  // 128
#define RSTG 16
#define NSTG (CHUNK_S / RSTG)     // 8

// ---------------- device scratch ----------------
__device__ __align__(128) __nv_bfloat16 g_whi[(size_t)H_DIM * H_DIM]; // pre-swizzled tiles
__device__ __align__(128) __nv_bfloat16 g_wlo[(size_t)H_DIM * H_DIM];
__device__ float g_norms[4 * M_ROWS];      // per-bn partial row sumsq of z
__device__ float g_b[M_ROWS];
__device__ float g_u[C_CAPS * H_DIM];      // u_c = W^T c_prev
__device__ float g_bc[C_CAPS];             // bias . c_prev
__device__ float g_Mp[C_CAPS * NCHUNK];
__device__ float g_Zp[C_CAPS * NCHUNK];
__device__ float g_Wp[C_CAPS * NCHUNK];    // sum exp*scale partials
__device__ float g_Vp[(size_t)C_CAPS * NCHUNK * H_DIM];  // y partials

// ---------------- helpers ----------------
__device__ __forceinline__ uint32_t smem_u32(const void* p) {
    uint32_t a;
    asm("{ .reg .u64 t; cvta.to.shared.u64 t, %1; cvt.u32.u64 %0, t; }" : "=r"(a) : "l"(p));
    return a;
}
__device__ __forceinline__ void ldsm4(uint32_t* r, uint32_t addr) {
    asm volatile("ldmatrix.sync.aligned.m8n8.x4.shared.b16 {%0,%1,%2,%3}, [%4];"
        : "=r"(r[0]), "=r"(r[1]), "=r"(r[2]), "=r"(r[3]) : "r"(addr));
}
__device__ __forceinline__ void mma16816(float* d, const uint32_t* a, const uint32_t* b) {
    asm volatile("mma.sync.aligned.m16n8k16.row.col.f32.bf16.bf16.f32 "
        "{%0,%1,%2,%3}, {%4,%5,%6,%7}, {%8,%9}, {%0,%1,%2,%3};"
        : "+f"(d[0]), "+f"(d[1]), "+f"(d[2]), "+f"(d[3])
        : "r"(a[0]), "r"(a[1]), "r"(a[2]), "r"(a[3]), "r"(b[0]), "r"(b[1]));
}
__device__ __forceinline__ void sts128(uint32_t addr, uint4 v) {
    asm volatile("st.shared.v4.b32 [%0], {%1,%2,%3,%4};"
        :: "r"(addr), "r"(v.x), "r"(v.y), "r"(v.z), "r"(v.w) : "memory");
}
#define CP_ASYNC16(dst, src) \
    asm volatile("cp.async.cg.shared.global [%0], [%1], 16;" :: "r"(dst), "l"(src) : "memory")
#define CP_COMMIT() asm volatile("cp.async.commit_group;" ::: "memory")
#define CP_WAIT(n)  asm volatile("cp.async.wait_group %0;" :: "n"(n) : "memory")

__device__ __forceinline__ uint32_t packhi2(float x, float y) {
    __nv_bfloat16 hx = __float2bfloat16_rn(x);
    __nv_bfloat16 hy = __float2bfloat16_rn(y);
    return (uint32_t)__bfloat16_as_ushort(hy) << 16 | __bfloat16_as_ushort(hx);
}
// swizzled byte offset inside an 8KB [128 x 32] bf16 tile; kc = 16B chunk (0..3)
__device__ __forceinline__ uint32_t tswz(uint32_t row, uint32_t kc) {
    return row * 64u + ((kc ^ ((row >> 1) & 3u)) << 4);
}

// ============================================================================
// convw: W fp32 -> pre-swizzled bf16 hi/lo tiles matching the GEMM's B smem
// layout exactly. Tile (bn,kt) is an 8KB block [128 n-rows x 32 k].
// ============================================================================
__global__ void convw_kernel(const float* __restrict__ W) {
    int g = blockIdx.x * 256 + threadIdx.x;   // 0..65535 chunks of 4 floats
    int n = g >> 7, ch = g & 127;
    int kt = ch >> 3, kc = (ch >> 1) & 3, half = ch & 1;
    int bn = n >> 7, nrow = n & 127;
    float4 v = *(const float4*)&W[(size_t)n * 512 + ch * 4];
    __nv_bfloat16 h0 = __float2bfloat16_rn(v.x), h1 = __float2bfloat16_rn(v.y);
    __nv_bfloat16 h2 = __float2bfloat16_rn(v.z), h3 = __float2bfloat16_rn(v.w);
    uint2 hi, lo;
    hi.x = (uint32_t)__bfloat16_as_ushort(h1) << 16 | __bfloat16_as_ushort(h0);
    hi.y = (uint32_t)__bfloat16_as_ushort(h3) << 16 | __bfloat16_as_ushort(h2);
    lo.x = packhi2(v.x - __bfloat162float(h0), v.y - __bfloat162float(h1));
    lo.y = packhi2(v.z - __bfloat162float(h2), v.w - __bfloat162float(h3));
    size_t dst = ((size_t)(bn * 16 + kt) << 13) + tswz(nrow, kc) + half * 8;
    *(uint2*)((char*)g_whi + dst) = hi;
    *(uint2*)((char*)g_wlo + dst) = lo;
}

// ============================================================================
// GEMM (norms only): z = x@W^T + bias; writes per-bn partial row sum-of-squares.
// 2-product split: xh*Wh + xh*Wl. Tile 128x128, BK=32, 8 warps.
// Stage = Ah 8K | Bh 8K | Bl 8K. B streamed via cp.async from pre-swizzled W.
// ============================================================================
#define GSM_STAGE 24576
#define GSM_TOTAL (2 * GSM_STAGE + 512)

__device__ __forceinline__ void issueB(uint32_t stg, int bn, int kt, int t) {
    size_t tile = (size_t)(bn * 16 + kt) << 13;
    const char* sh = (const char*)g_whi + tile + t * 32;
    const char* sl = (const char*)g_wlo + tile + t * 32;
    CP_ASYNC16(stg + 8192 + t * 32, sh);
    CP_ASYNC16(stg + 8192 + t * 32 + 16, sh + 16);
    CP_ASYNC16(stg + 16384 + t * 32, sl);
    CP_ASYNC16(stg + 16384 + t * 32 + 16, sl + 16);
}

__global__ void __launch_bounds__(256, 1) gemm_norms(
    const float* __restrict__ x, const float* __restrict__ bias)
{
    extern __shared__ __align__(1024) char smem[];
    const uint32_t sb = smem_u32(smem);

    const int t = threadIdx.x, l = t & 31, wid = t >> 5;
    const int wm = wid & 3, wn = wid >> 2;
    const int bn = blockIdx.x, mtile = blockIdx.y;

    const int c0row = t >> 2, ckc = t & 3;
    const float* ag0 = x + ((size_t)mtile * 128 + c0row) * 512 + ckc * 8;
    const float* ag1 = x + ((size_t)mtile * 128 + c0row + 64) * 512 + ckc * 8;
    const uint32_t so0 = tswz(c0row, ckc);
    const uint32_t so1 = tswz(c0row + 64, ckc);

    uint32_t aoffA[2][2], aoffB[4][2];
#pragma unroll
    for (int mt = 0; mt < 2; mt++)
#pragma unroll
        for (int ks = 0; ks < 2; ks++) {
            uint32_t m = wm * 32 + mt * 16 + ((l >> 3) & 1) * 8 + (l & 7);
            aoffA[mt][ks] = tswz(m, ks * 2 + (l >> 4));
        }
#pragma unroll
    for (int nt2 = 0; nt2 < 4; nt2++)
#pragma unroll
        for (int ks = 0; ks < 2; ks++) {
            uint32_t n = wn * 64 + nt2 * 16 + ((l >> 4) & 1) * 8 + (l & 7);
            aoffB[nt2][ks] = tswz(n, ks * 2 + ((l >> 3) & 1));
        }

    float acc[2][8][4];
#pragma unroll
    for (int mt = 0; mt < 2; mt++)
#pragma unroll
        for (int nt = 0; nt < 8; nt++)
#pragma unroll
            for (int k = 0; k < 4; k++) acc[mt][nt][k] = 0.f;

    // prologue
    issueB(sb, bn, 0, t);
    CP_COMMIT();
    float4 pa[2][2];
    pa[0][0] = *(const float4*)(ag0); pa[0][1] = *(const float4*)(ag0 + 4);
    pa[1][0] = *(const float4*)(ag1); pa[1][1] = *(const float4*)(ag1 + 4);

    for (int kt = 0; kt < 16; kt++) {
        const uint32_t stg = sb + (kt & 1) * GSM_STAGE;

        // store A hi (converted)
        {
            uint4 h0, h1;
            h0.x = packhi2(pa[0][0].x, pa[0][0].y); h0.y = packhi2(pa[0][0].z, pa[0][0].w);
            h0.z = packhi2(pa[0][1].x, pa[0][1].y); h0.w = packhi2(pa[0][1].z, pa[0][1].w);
            h1.x = packhi2(pa[1][0].x, pa[1][0].y); h1.y = packhi2(pa[1][0].z, pa[1][0].w);
            h1.z = packhi2(pa[1][1].x, pa[1][1].y); h1.w = packhi2(pa[1][1].z, pa[1][1].w);
            sts128(stg + so0, h0);
            sts128(stg + so1, h1);
        }
        if (kt < 15) {
            issueB(sb + ((kt + 1) & 1) * GSM_STAGE, bn, kt + 1, t);
            CP_COMMIT();
            CP_WAIT(1);
        } else {
            CP_WAIT(0);
        }
        __syncthreads();

        if (kt < 15) {
            int ko = (kt + 1) * 32;
            pa[0][0] = *(const float4*)(ag0 + ko); pa[0][1] = *(const float4*)(ag0 + ko + 4);
            pa[1][0] = *(const float4*)(ag1 + ko); pa[1][1] = *(const float4*)(ag1 + ko + 4);
        }

#pragma unroll
        for (int ks = 0; ks < 2; ks++) {
            uint32_t ah[2][4], bh[4][4], bl[4][4];
#pragma unroll
            for (int mt = 0; mt < 2; mt++) ldsm4(ah[mt], stg + aoffA[mt][ks]);
#pragma unroll
            for (int nt2 = 0; nt2 < 4; nt2++) {
                ldsm4(bh[nt2], stg + 8192 + aoffB[nt2][ks]);
                ldsm4(bl[nt2], stg + 16384 + aoffB[nt2][ks]);
            }
#pragma unroll
            for (int mt = 0; mt < 2; mt++)
#pragma unroll
                for (int nt = 0; nt < 8; nt++) {
                    mma16816(acc[mt][nt], ah[mt], &bh[nt >> 1][(nt & 1) * 2]);
                    mma16816(acc[mt][nt], ah[mt], &bl[nt >> 1][(nt & 1) * 2]);
                }
        }
        __syncthreads();
    }

    // ---- epilogue: bias add + row-norm partials only ----
    float* norm_sm = (float*)(smem + 2 * GSM_STAGE);
    if (t < 128) norm_sm[t] = 0.f;
    __syncthreads();

    float2 bias2[8];
#pragma unroll
    for (int nt = 0; nt < 8; nt++)
        bias2[nt] = *(const float2*)&bias[bn * 128 + wn * 64 + nt * 8 + (l & 3) * 2];

#pragma unroll
    for (int mt = 0; mt < 2; mt++)
#pragma unroll
        for (int half = 0; half < 2; half++) {
            int r = wm * 32 + mt * 16 + (l >> 2) + half * 8;
            float ss = 0.f;
#pragma unroll
            for (int nt = 0; nt < 8; nt++) {
                float vx = acc[mt][nt][half * 2]     + bias2[nt].x;
                float vy = acc[mt][nt][half * 2 + 1] + bias2[nt].y;
                ss += vx * vx + vy * vy;
            }
            ss += __shfl_xor_sync(0xffffffffu, ss, 1);
            ss += __shfl_xor_sync(0xffffffffu, ss, 2);
            if ((l & 3) == 0) atomicAdd(&norm_sm[r], ss);
        }
    __syncthreads();
    if (t < 128)
        g_norms[(size_t)bn * M_ROWS + (size_t)mtile * 128 + t] = norm_sm[t];
}

// ============================================================================
// Sweep: one fused routing iteration over x.
//   dot_s = x_s . u_c ;  b_s += scale_s*(dot+bc) ;  online softmax ;
//   y += exp(b-M)*scale * x_s ; writes chunk partials (M, Z, Wsum, y[512]).
// ============================================================================
__global__ void __launch_bounds__(256) sweep_pass(const float* __restrict__ x, int do_dot) {
    const int c = blockIdx.y, chunk = blockIdx.x;
    const int t = threadIdx.x, wid = t >> 5, lane = t & 31;

    __shared__ float tile[RSTG][512];
    __shared__ float usm[512];
    __shared__ float bst[RSTG], sst[RSTG], wst[RSTG];
    __shared__ float runMs, Zsh, Wsh, fsh, bcs;

    usm[t]       = do_dot ? g_u[c * 512 + t] : 0.f;
    usm[t + 256] = do_dot ? g_u[c * 512 + t + 256] : 0.f;
    if (t == 0) { runMs = -1e30f; Zsh = 0.f; Wsh = 0.f; bcs = do_dot ? g_bc[c] : 0.f; }

    const size_t rowbase = (size_t)c * S_DIM + (size_t)chunk * CHUNK_S;
    float ax = 0.f, ay = 0.f;
    __syncthreads();

    for (int st = 0; st < NSTG; st++) {
        const float4* gsrc = (const float4*)(x + (rowbase + st * RSTG) * 512);
        float4* td = (float4*)&tile[0][0];
#pragma unroll
        for (int i = 0; i < 8; i++) td[t + 256 * i] = gsrc[t + 256 * i];
        __syncthreads();

#pragma unroll
        for (int rr = 0; rr < 2; rr++) {
            int rl = wid * 2 + rr;
            float dot = 0.f;
            if (do_dot) {
                const float4* tr = (const float4*)&tile[rl][0];
#pragma unroll
                for (int j = 0; j < 4; j++) {
                    float4 v = tr[lane + 32 * j];
                    float4 cv = *(const float4*)&usm[(lane + 32 * j) * 4];
                    dot += v.x * cv.x + v.y * cv.y + v.z * cv.z + v.w * cv.w;
                }
#pragma unroll
                for (int off = 16; off > 0; off >>= 1)
                    dot += __shfl_xor_sync(0xffffffffu, dot, off);
            }
            if (lane == 0) {
                size_t row = rowbase + st * RSTG + rl;
                float sq = g_norms[row] + g_norms[M_ROWS + row]
                         + g_norms[2 * M_ROWS + row] + g_norms[3 * M_ROWS + row];
                float scale = (sq / (1.f + sq)) * rsqrtf(sq + 1e-7f);
                float bv;
                if (do_dot) {
                    bv = g_b[row] + scale * (dot + bcs);
                    g_b[row] = bv;
                } else {
                    bv = g_b[row];   // zero
                }
                bst[rl] = bv;
                sst[rl] = scale;
            }
        }
        __syncthreads();

        if (t < 32) {
            float v = (lane < RSTG) ? bst[lane] : -1e30f;
            float m = v;
#pragma unroll
            for (int off = 16; off > 0; off >>= 1)
                m = fmaxf(m, __shfl_xor_sync(0xffffffffu, m, off));
            float rm = runMs;
            float nm = fmaxf(rm, m);
            float w = __expf(v - nm);
            float zst = w;
#pragma unroll
            for (int off = 16; off > 0; off >>= 1)
                zst += __shfl_xor_sync(0xffffffffu, zst, off);
            float wsv = (lane < RSTG) ? w * sst[lane] : 0.f;
            float wss = wsv;
#pragma unroll
            for (int off = 16; off > 0; off >>= 1)
                wss += __shfl_xor_sync(0xffffffffu, wss, off);
            if (lane < RSTG) wst[lane] = wsv;
            if (lane == 0) {
                float f = __expf(rm - nm);
                fsh = f;
                Zsh = Zsh * f + zst;
                Wsh = Wsh * f + wss;
                runMs = nm;
            }
        }
        __syncthreads();

        float f = fsh;
        ax *= f; ay *= f;
#pragma unroll
        for (int r = 0; r < RSTG; r++) {
            float w = wst[r];
            float2 v = *(const float2*)&tile[r][2 * t];
            ax += w * v.x;
            ay += w * v.y;
        }
        __syncthreads();
    }

    int pc = c * NCHUNK + chunk;
    *(float2*)&g_Vp[(size_t)pc * 512 + 2 * t] = make_float2(ax, ay);
    if (t == 0) { g_Mp[pc] = runMs; g_Zp[pc] = Zsh; g_Wp[pc] = Wsh; }
}

// ============================================================================
// Combine: y partials -> y; craw = y@W^T + bias*wsum; c = squash(craw);
// if not last: u = W^T c, bc = bias.c ; else write c to output.
// ============================================================================
__global__ void __launch_bounds__(256) combine_kernel(
    const float* __restrict__ W, const float* __restrict__ bias,
    float* __restrict__ dst, int last)
{
    const int c = blockIdx.x, t = threadIdx.x;
    const int wid = t >> 5, lane = t & 31;

    __shared__ float yv[512];
    __shared__ float craw[512];
    __shared__ float csm[512];
    __shared__ float sk[NCHUNK];
    __shared__ float red[8];
    __shared__ float Zs, Wts, Sq;

    if (t == 0) {
        float M = g_Mp[c * NCHUNK];
#pragma unroll
        for (int k = 1; k < NCHUNK; k++) M = fmaxf(M, g_Mp[c * NCHUNK + k]);
        float Z = 0.f, Wt = 0.f;
#pragma unroll
        for (int k = 0; k < NCHUNK; k++) {
            float e = __expf(g_Mp[c * NCHUNK + k] - M);
            sk[k] = e;
            Z  += g_Zp[c * NCHUNK + k] * e;
            Wt += g_Wp[c * NCHUNK + k] * e;
        }
        Zs = Z;
        Wts = Wt / Z;
    }
    __syncthreads();

    float w0 = 0.f, w1 = 0.f;
#pragma unroll
    for (int k = 0; k < NCHUNK; k++) {
        float e = sk[k];
        float2 v = *(const float2*)&g_Vp[((size_t)(c * NCHUNK + k)) * 512 + 2 * t];
        w0 += e * v.x;
        w1 += e * v.y;
    }
    float invZ = 1.f / Zs;
    yv[2 * t] = w0 * invZ;
    yv[2 * t + 1] = w1 * invZ;
    __syncthreads();

    // craw[o] = yv . W[o] + bias[o]*Wts   (warp per 64 outputs)
    for (int i = 0; i < 64; i++) {
        int o = wid * 64 + i;
        const float4* wr = (const float4*)(W + (size_t)o * 512);
        float d = 0.f;
#pragma unroll
        for (int g = 0; g < 4; g++) {
            float4 a = wr[lane + 32 * g];
            float4 b = *(const float4*)&yv[(lane + 32 * g) * 4];
            d += a.x * b.x + a.y * b.y + a.z * b.z + a.w * b.w;
        }
#pragma unroll
        for (int off = 16; off > 0; off >>= 1)
            d += __shfl_xor_sync(0xffffffffu, d, off);
        if (lane == 0) craw[o] = d + bias[o] * Wts;
    }
    __syncthreads();

    float s2 = craw[t] * craw[t] + craw[t + 256] * craw[t + 256];
#pragma unroll
    for (int off = 16; off > 0; off >>= 1)
        s2 += __shfl_xor_sync(0xffffffffu, s2, off);
    if (lane == 0) red[wid] = s2;
    __syncthreads();
    if (t == 0) {
        float ss = 0.f;
#pragma unroll
        for (int k = 0; k < 8; k++) ss += red[k];
        Sq = ss;
    }
    __syncthreads();

    float sq = Sq;
    float scale = (sq / (1.f + sq)) * rsqrtf(sq + 1e-7f);
    float c0 = scale * craw[t], c1 = scale * craw[t + 256];

    if (last) {
        dst[c * 512 + t] = c0;
        dst[c * 512 + t + 256] = c1;
        return;
    }
    csm[t] = c0;
    csm[t + 256] = c1;
    __syncthreads();

    // u = W^T c  (coalesced row-broadcast loop)
    float u0 = 0.f, u1 = 0.f;
#pragma unroll 4
    for (int o = 0; o < 512; o++) {
        float co = csm[o];
        float2 wv = *(const float2*)&W[(size_t)o * 512 + 2 * t];
        u0 += co * wv.x;
        u1 += co * wv.y;
    }
    g_u[c * 512 + 2 * t] = u0;
    g_u[c * 512 + 2 * t + 1] = u1;

    // bc = bias . c
    float p = bias[t] * csm[t] + bias[t + 256] * csm[t + 256];
#pragma unroll
    for (int off = 16; off > 0; off >>= 1)
        p += __shfl_xor_sync(0xffffffffu, p, off);
    if (lane == 0) red[wid] = p;
    __syncthreads();
    if (t == 0) {
        float pp = 0.f;
#pragma unroll
        for (int k = 0; k < 8; k++) pp += red[k];
        g_bc[c] = pp;
    }
}

// ============================================================================
extern "C" void kernel_launch(void* const* d_in, const int* in_sizes, int n_in,
                              void* d_out, int out_size) {
    const float* x    = (const float*)d_in[0];
    const float* W    = (const float*)d_in[1];
    const float* bias = (const float*)d_in[2];
    float* out = (float*)d_out;

    void* pb = nullptr; cudaGetSymbolAddress(&pb, g_b);
    cudaMemsetAsync(pb, 0, (size_t)M_ROWS * sizeof(float));

    convw_kernel<<<256, 256>>>(W);

    static bool attr_done = false;
    if (!attr_done) {
        cudaFuncSetAttribute(gemm_norms, cudaFuncAttributeMaxDynamicSharedMemorySize, GSM_TOTAL);
        attr_done = true;
    }
    gemm_norms<<<dim3(4, 1024), 256, GSM_TOTAL>>>(x, bias);

    for (int it = 0; it < 3; ++it) {
        sweep_pass<<<dim3(NCHUNK, C_CAPS), 256>>>(x, it > 0 ? 1 : 0);
        combine_kernel<<<C_CAPS, 256>>>(W, bias, out, it == 2 ? 1 : 0);
    }
}

// round 5
// speedup vs baseline: 1.8139x; 1.1862x over previous
#include <cuda_runtime.h>
#include <cuda_bf16.h>
#include <cstdint>

#define C_CAPS 64
#define S_DIM 2048
#define H_DIM 512
#define M_ROWS (C_CAPS * S_DIM)   // 131072
#define NCHUNK 16
#define CHUNK_S (S_DIM / NCHUNK)  // 128
#define RSTG 32
#define NSTG (CHUNK_S / RSTG)     // 4

// ---------------- device scratch ----------------
__device__ __align__(128) __nv_bfloat16 g_whi[(size_t)H_DIM * H_DIM];
__device__ __align__(128) __nv_bfloat16 g_wlo[(size_t)H_DIM * H_DIM];
__device__ float g_norms[4 * M_ROWS];
__device__ float g_b[M_ROWS];
__device__ float g_u[C_CAPS * H_DIM];
__device__ float g_bc[C_CAPS];
__device__ float g_Mp[C_CAPS * NCHUNK];
__device__ float g_Zp[C_CAPS * NCHUNK];
__device__ float g_Wp[C_CAPS * NCHUNK];
__device__ float g_Vp[(size_t)C_CAPS * NCHUNK * H_DIM];
__device__ float g_y[C_CAPS * H_DIM];
__device__ float g_wts[C_CAPS];
__device__ float g_craw[C_CAPS * H_DIM];
__device__ float g_sqp[C_CAPS * 4];

// ---------------- helpers ----------------
__device__ __forceinline__ uint32_t smem_u32(const void* p) {
    uint32_t a;
    asm("{ .reg .u64 t; cvta.to.shared.u64 t, %1; cvt.u32.u64 %0, t; }" : "=r"(a) : "l"(p));
    return a;
}
__device__ __forceinline__ void ldsm4(uint32_t* r, uint32_t addr) {
    asm volatile("ldmatrix.sync.aligned.m8n8.x4.shared.b16 {%0,%1,%2,%3}, [%4];"
        : "=r"(r[0]), "=r"(r[1]), "=r"(r[2]), "=r"(r[3]) : "r"(addr));
}
__device__ __forceinline__ void mma16816(float* d, const uint32_t* a, const uint32_t* b) {
    asm volatile("mma.sync.aligned.m16n8k16.row.col.f32.bf16.bf16.f32 "
        "{%0,%1,%2,%3}, {%4,%5,%6,%7}, {%8,%9}, {%0,%1,%2,%3};"
        : "+f"(d[0]), "+f"(d[1]), "+f"(d[2]), "+f"(d[3])
        : "r"(a[0]), "r"(a[1]), "r"(a[2]), "r"(a[3]), "r"(b[0]), "r"(b[1]));
}
__device__ __forceinline__ void sts128(uint32_t addr, uint4 v) {
    asm volatile("st.shared.v4.b32 [%0], {%1,%2,%3,%4};"
        :: "r"(addr), "r"(v.x), "r"(v.y), "r"(v.z), "r"(v.w) : "memory");
}
#define CP_ASYNC16(dst, src) \
    asm volatile("cp.async.cg.shared.global [%0], [%1], 16;" :: "r"(dst), "l"(src) : "memory")
#define CP_COMMIT() asm volatile("cp.async.commit_group;" ::: "memory")
#define CP_WAIT(n)  asm volatile("cp.async.wait_group %0;" :: "n"(n) : "memory")

__device__ __forceinline__ uint32_t packhi2(float x, float y) {
    __nv_bfloat16 hx = __float2bfloat16_rn(x);
    __nv_bfloat16 hy = __float2bfloat16_rn(y);
    return (uint32_t)__bfloat16_as_ushort(hy) << 16 | __bfloat16_as_ushort(hx);
}
__device__ __forceinline__ uint32_t tswz(uint32_t row, uint32_t kc) {
    return row * 64u + ((kc ^ ((row >> 1) & 3u)) << 4);
}

// ============================================================================
// convw: W fp32 -> pre-swizzled bf16 hi/lo tiles (8KB blocks [128 x 32]).
// ============================================================================
__global__ void convw_kernel(const float* __restrict__ W) {
    int g = blockIdx.x * 256 + threadIdx.x;
    int n = g >> 7, ch = g & 127;
    int kt = ch >> 3, kc = (ch >> 1) & 3, half = ch & 1;
    int bn = n >> 7, nrow = n & 127;
    float4 v = *(const float4*)&W[(size_t)n * 512 + ch * 4];
    __nv_bfloat16 h0 = __float2bfloat16_rn(v.x), h1 = __float2bfloat16_rn(v.y);
    __nv_bfloat16 h2 = __float2bfloat16_rn(v.z), h3 = __float2bfloat16_rn(v.w);
    uint2 hi, lo;
    hi.x = (uint32_t)__bfloat16_as_ushort(h1) << 16 | __bfloat16_as_ushort(h0);
    hi.y = (uint32_t)__bfloat16_as_ushort(h3) << 16 | __bfloat16_as_ushort(h2);
    lo.x = packhi2(v.x - __bfloat162float(h0), v.y - __bfloat162float(h1));
    lo.y = packhi2(v.z - __bfloat162float(h2), v.w - __bfloat162float(h3));
    size_t dst = ((size_t)(bn * 16 + kt) << 13) + tswz(nrow, kc) + half * 8;
    *(uint2*)((char*)g_whi + dst) = hi;
    *(uint2*)((char*)g_wlo + dst) = lo;
}

// ============================================================================
// GEMM (norms only): 2-product split xh*(Wh+Wl). Tile 128x128, BK=32, 8 warps.
// ============================================================================
#define GSM_STAGE 24576
#define GSM_TOTAL (2 * GSM_STAGE + 512)

__device__ __forceinline__ void issueB(uint32_t stg, int bn, int kt, int t) {
    size_t tile = (size_t)(bn * 16 + kt) << 13;
    const char* sh = (const char*)g_whi + tile + t * 32;
    const char* sl = (const char*)g_wlo + tile + t * 32;
    CP_ASYNC16(stg + 8192 + t * 32, sh);
    CP_ASYNC16(stg + 8192 + t * 32 + 16, sh + 16);
    CP_ASYNC16(stg + 16384 + t * 32, sl);
    CP_ASYNC16(stg + 16384 + t * 32 + 16, sl + 16);
}

__global__ void __launch_bounds__(256, 1) gemm_norms(
    const float* __restrict__ x, const float* __restrict__ bias)
{
    extern __shared__ __align__(1024) char smem[];
    const uint32_t sb = smem_u32(smem);

    const int t = threadIdx.x, l = t & 31, wid = t >> 5;
    const int wm = wid & 3, wn = wid >> 2;
    const int bn = blockIdx.x, mtile = blockIdx.y;

    const int c0row = t >> 2, ckc = t & 3;
    const float* ag0 = x + ((size_t)mtile * 128 + c0row) * 512 + ckc * 8;
    const float* ag1 = x + ((size_t)mtile * 128 + c0row + 64) * 512 + ckc * 8;
    const uint32_t so0 = tswz(c0row, ckc);
    const uint32_t so1 = tswz(c0row + 64, ckc);

    uint32_t aoffA[2][2], aoffB[4][2];
#pragma unroll
    for (int mt = 0; mt < 2; mt++)
#pragma unroll
        for (int ks = 0; ks < 2; ks++) {
            uint32_t m = wm * 32 + mt * 16 + ((l >> 3) & 1) * 8 + (l & 7);
            aoffA[mt][ks] = tswz(m, ks * 2 + (l >> 4));
        }
#pragma unroll
    for (int nt2 = 0; nt2 < 4; nt2++)
#pragma unroll
        for (int ks = 0; ks < 2; ks++) {
            uint32_t n = wn * 64 + nt2 * 16 + ((l >> 4) & 1) * 8 + (l & 7);
            aoffB[nt2][ks] = tswz(n, ks * 2 + ((l >> 3) & 1));
        }

    float acc[2][8][4];
#pragma unroll
    for (int mt = 0; mt < 2; mt++)
#pragma unroll
        for (int nt = 0; nt < 8; nt++)
#pragma unroll
            for (int k = 0; k < 4; k++) acc[mt][nt][k] = 0.f;

    issueB(sb, bn, 0, t);
    CP_COMMIT();
    float4 pa[2][2];
    pa[0][0] = *(const float4*)(ag0); pa[0][1] = *(const float4*)(ag0 + 4);
    pa[1][0] = *(const float4*)(ag1); pa[1][1] = *(const float4*)(ag1 + 4);

    for (int kt = 0; kt < 16; kt++) {
        const uint32_t stg = sb + (kt & 1) * GSM_STAGE;
        {
            uint4 h0, h1;
            h0.x = packhi2(pa[0][0].x, pa[0][0].y); h0.y = packhi2(pa[0][0].z, pa[0][0].w);
            h0.z = packhi2(pa[0][1].x, pa[0][1].y); h0.w = packhi2(pa[0][1].z, pa[0][1].w);
            h1.x = packhi2(pa[1][0].x, pa[1][0].y); h1.y = packhi2(pa[1][0].z, pa[1][0].w);
            h1.z = packhi2(pa[1][1].x, pa[1][1].y); h1.w = packhi2(pa[1][1].z, pa[1][1].w);
            sts128(stg + so0, h0);
            sts128(stg + so1, h1);
        }
        if (kt < 15) {
            issueB(sb + ((kt + 1) & 1) * GSM_STAGE, bn, kt + 1, t);
            CP_COMMIT();
            CP_WAIT(1);
        } else {
            CP_WAIT(0);
        }
        __syncthreads();

        if (kt < 15) {
            int ko = (kt + 1) * 32;
            pa[0][0] = *(const float4*)(ag0 + ko); pa[0][1] = *(const float4*)(ag0 + ko + 4);
            pa[1][0] = *(const float4*)(ag1 + ko); pa[1][1] = *(const float4*)(ag1 + ko + 4);
        }

#pragma unroll
        for (int ks = 0; ks < 2; ks++) {
            uint32_t ah[2][4], bh[4][4], bl[4][4];
#pragma unroll
            for (int mt = 0; mt < 2; mt++) ldsm4(ah[mt], stg + aoffA[mt][ks]);
#pragma unroll
            for (int nt2 = 0; nt2 < 4; nt2++) {
                ldsm4(bh[nt2], stg + 8192 + aoffB[nt2][ks]);
                ldsm4(bl[nt2], stg + 16384 + aoffB[nt2][ks]);
            }
#pragma unroll
            for (int mt = 0; mt < 2; mt++)
#pragma unroll
                for (int nt = 0; nt < 8; nt++) {
                    mma16816(acc[mt][nt], ah[mt], &bh[nt >> 1][(nt & 1) * 2]);
                    mma16816(acc[mt][nt], ah[mt], &bl[nt >> 1][(nt & 1) * 2]);
                }
        }
        __syncthreads();
    }

    float* norm_sm = (float*)(smem + 2 * GSM_STAGE);
    if (t < 128) norm_sm[t] = 0.f;
    __syncthreads();

    float2 bias2[8];
#pragma unroll
    for (int nt = 0; nt < 8; nt++)
        bias2[nt] = *(const float2*)&bias[bn * 128 + wn * 64 + nt * 8 + (l & 3) * 2];

#pragma unroll
    for (int mt = 0; mt < 2; mt++)
#pragma unroll
        for (int half = 0; half < 2; half++) {
            int r = wm * 32 + mt * 16 + (l >> 2) + half * 8;
            float ss = 0.f;
#pragma unroll
            for (int nt = 0; nt < 8; nt++) {
                float vx = acc[mt][nt][half * 2]     + bias2[nt].x;
                float vy = acc[mt][nt][half * 2 + 1] + bias2[nt].y;
                ss += vx * vx + vy * vy;
            }
            ss += __shfl_xor_sync(0xffffffffu, ss, 1);
            ss += __shfl_xor_sync(0xffffffffu, ss, 2);
            if ((l & 3) == 0) atomicAdd(&norm_sm[r], ss);
        }
    __syncthreads();
    if (t < 128)
        g_norms[(size_t)bn * M_ROWS + (size_t)mtile * 128 + t] = norm_sm[t];
}

// ============================================================================
// Sweep: cp.async double-buffered, 32-row stages. Chunk partials out.
// Dynamic smem: 2 x 32 x 512 floats = 128 KB.
// ============================================================================
#define SWEEP_SMEM (2 * RSTG * 512 * 4)

__global__ void __launch_bounds__(256) sweep_pass(const float* __restrict__ x, int do_dot) {
    extern __shared__ __align__(16) float tiles[];
    __shared__ float usm[512];
    __shared__ float bst[RSTG], sst[RSTG], wst[RSTG];
    __shared__ float runMs, Zsh, Wsh, fsh, bcs;

    const int c = blockIdx.y, chunk = blockIdx.x;
    const int t = threadIdx.x, wid = t >> 5, lane = t & 31;

    usm[t]       = do_dot ? g_u[c * 512 + t] : 0.f;
    usm[t + 256] = do_dot ? g_u[c * 512 + t + 256] : 0.f;
    if (t == 0) { runMs = -1e30f; Zsh = 0.f; Wsh = 0.f; bcs = do_dot ? g_bc[c] : 0.f; }

    const size_t rowbase = (size_t)c * S_DIM + (size_t)chunk * CHUNK_S;
    float ax = 0.f, ay = 0.f;

    // prologue: stage 0
    {
        const float* src = x + rowbase * 512;
        uint32_t dst = smem_u32(tiles);
#pragma unroll
        for (int i = 0; i < 16; i++) {
            int idx = t + 256 * i;
            CP_ASYNC16(dst + idx * 16, src + idx * 4);
        }
        CP_COMMIT();
    }

    for (int st = 0; st < NSTG; st++) {
        CP_WAIT(0);
        __syncthreads();
        float* tile = tiles + (st & 1) * (RSTG * 512);

        if (st < NSTG - 1) {
            const float* src = x + (rowbase + (size_t)(st + 1) * RSTG) * 512;
            uint32_t dst = smem_u32(tiles + ((st + 1) & 1) * (RSTG * 512));
#pragma unroll
            for (int i = 0; i < 16; i++) {
                int idx = t + 256 * i;
                CP_ASYNC16(dst + idx * 16, src + idx * 4);
            }
            CP_COMMIT();
        }

        // dots: each warp handles 4 rows
#pragma unroll
        for (int rr = 0; rr < 4; rr++) {
            int rl = wid * 4 + rr;
            float dot = 0.f;
            if (do_dot) {
                const float4* tr = (const float4*)(tile + rl * 512);
#pragma unroll
                for (int j = 0; j < 4; j++) {
                    float4 v = tr[lane + 32 * j];
                    float4 cv = *(const float4*)&usm[(lane + 32 * j) * 4];
                    dot += v.x * cv.x + v.y * cv.y + v.z * cv.z + v.w * cv.w;
                }
#pragma unroll
                for (int off = 16; off > 0; off >>= 1)
                    dot += __shfl_xor_sync(0xffffffffu, dot, off);
            }
            if (lane == 0) {
                size_t row = rowbase + st * RSTG + rl;
                float sq = g_norms[row] + g_norms[M_ROWS + row]
                         + g_norms[2 * M_ROWS + row] + g_norms[3 * M_ROWS + row];
                float scale = (sq / (1.f + sq)) * rsqrtf(sq + 1e-7f);
                float bv;
                if (do_dot) {
                    bv = g_b[row] + scale * (dot + bcs);
                    g_b[row] = bv;
                } else {
                    bv = 0.f;
                }
                bst[rl] = bv;
                sst[rl] = scale;
            }
        }
        __syncthreads();

        if (t < 32) {
            float v = bst[lane];
            float m = v;
#pragma unroll
            for (int off = 16; off > 0; off >>= 1)
                m = fmaxf(m, __shfl_xor_sync(0xffffffffu, m, off));
            float rm = runMs;
            float nm = fmaxf(rm, m);
            float w = __expf(v - nm);
            float zst = w;
#pragma unroll
            for (int off = 16; off > 0; off >>= 1)
                zst += __shfl_xor_sync(0xffffffffu, zst, off);
            float wsv = w * sst[lane];
            float wss = wsv;
#pragma unroll
            for (int off = 16; off > 0; off >>= 1)
                wss += __shfl_xor_sync(0xffffffffu, wss, off);
            wst[lane] = wsv;
            if (lane == 0) {
                float f = __expf(rm - nm);
                fsh = f;
                Zsh = Zsh * f + zst;
                Wsh = Wsh * f + wss;
                runMs = nm;
            }
        }
        __syncthreads();

        float f = fsh;
        ax *= f; ay *= f;
#pragma unroll
        for (int r = 0; r < RSTG; r++) {
            float w = wst[r];
            float2 v = *(const float2*)(tile + r * 512 + 2 * t);
            ax += w * v.x;
            ay += w * v.y;
        }
        // no trailing sync: top-of-loop syncthreads protects buffers
    }

    int pc = c * NCHUNK + chunk;
    *(float2*)&g_Vp[(size_t)pc * 512 + 2 * t] = make_float2(ax, ay);
    if (t == 0) { g_Mp[pc] = runMs; g_Zp[pc] = Zsh; g_Wp[pc] = Wsh; }
}

// ============================================================================
// K1: reduce chunk partials -> y[c,512], wts[c]
// ============================================================================
__global__ void __launch_bounds__(256) reduce_y() {
    const int c = blockIdx.x, t = threadIdx.x;
    __shared__ float sk[NCHUNK];
    __shared__ float Zs;

    if (t == 0) {
        float M = g_Mp[c * NCHUNK];
#pragma unroll
        for (int k = 1; k < NCHUNK; k++) M = fmaxf(M, g_Mp[c * NCHUNK + k]);
        float Z = 0.f, Wt = 0.f;
#pragma unroll
        for (int k = 0; k < NCHUNK; k++) {
            float e = __expf(g_Mp[c * NCHUNK + k] - M);
            sk[k] = e;
            Z  += g_Zp[c * NCHUNK + k] * e;
            Wt += g_Wp[c * NCHUNK + k] * e;
        }
        Zs = Z;
        g_wts[c] = Wt / Z;
    }
    __syncthreads();

    float w0 = 0.f, w1 = 0.f;
#pragma unroll
    for (int k = 0; k < NCHUNK; k++) {
        float e = sk[k];
        float2 v = *(const float2*)&g_Vp[((size_t)(c * NCHUNK + k)) * 512 + 2 * t];
        w0 += e * v.x;
        w1 += e * v.y;
    }
    float invZ = 1.f / Zs;
    *(float2*)&g_y[c * 512 + 2 * t] = make_float2(w0 * invZ, w1 * invZ);
}

// ============================================================================
// K2: craw[c,o] = y_c . W_o + bias_o * wts_c ; per-block partial sumsq.
// grid (4, 64): block = (output block ob, capsule c). Warp per 16 outputs.
// ============================================================================
__global__ void __launch_bounds__(256) cmat_kernel(
    const float* __restrict__ W, const float* __restrict__ bias)
{
    const int ob = blockIdx.x, c = blockIdx.y;
    const int t = threadIdx.x, wid = t >> 5, lane = t & 31;
    __shared__ float ysm[512];
    __shared__ float ssp[8];

    ysm[t]       = g_y[c * 512 + t];
    ysm[t + 256] = g_y[c * 512 + t + 256];
    __syncthreads();

    const float Wts = g_wts[c];
    float ss = 0.f;
#pragma unroll
    for (int i = 0; i < 16; i++) {
        int o = ob * 128 + wid * 16 + i;
        const float4* wr = (const float4*)(W + (size_t)o * 512);
        float d = 0.f;
#pragma unroll
        for (int g = 0; g < 4; g++) {
            float4 a = wr[lane + 32 * g];
            float4 b = *(const float4*)&ysm[(lane + 32 * g) * 4];
            d += a.x * b.x + a.y * b.y + a.z * b.z + a.w * b.w;
        }
#pragma unroll
        for (int off = 16; off > 0; off >>= 1)
            d += __shfl_xor_sync(0xffffffffu, d, off);
        if (lane == 0) {
            float cr = d + bias[o] * Wts;
            g_craw[c * 512 + o] = cr;
            ss += cr * cr;
        }
    }
    if (lane == 0) ssp[wid] = ss;
    __syncthreads();
    if (t == 0) {
        float s = 0.f;
#pragma unroll
        for (int k = 0; k < 8; k++) s += ssp[k];
        g_sqp[c * 4 + ob] = s;
    }
}

// ============================================================================
// K3: scale from sumsq; u[c,:] = scale * W^T craw_c ; bc = scale*(bias.craw).
// grid (4, 64): block = (h block ob, capsule c). o-loop split 4 ways.
// ============================================================================
__global__ void __launch_bounds__(256) ustep_kernel(
    const float* __restrict__ W, const float* __restrict__ bias)
{
    const int ob = blockIdx.x, c = blockIdx.y;
    const int t = threadIdx.x;
    const int og = t >> 6, cp = t & 63;

    __shared__ float csm[512];
    __shared__ float2 up[4][64];
    __shared__ float scsh;
    __shared__ float red2[8];

    csm[t]       = g_craw[c * 512 + t];
    csm[t + 256] = g_craw[c * 512 + t + 256];
    if (t == 0) {
        float sq = g_sqp[c * 4] + g_sqp[c * 4 + 1] + g_sqp[c * 4 + 2] + g_sqp[c * 4 + 3];
        scsh = (sq / (1.f + sq)) * rsqrtf(sq + 1e-7f);
    }
    __syncthreads();
    const float scale = scsh;

    float u0 = 0.f, u1 = 0.f;
    const float* wp = W + (size_t)(og * 128) * 512 + ob * 128 + cp * 2;
#pragma unroll 8
    for (int o = 0; o < 128; o++) {
        float co = csm[og * 128 + o];
        float2 wv = *(const float2*)(wp + (size_t)o * 512);
        u0 += co * wv.x;
        u1 += co * wv.y;
    }
    up[og][cp] = make_float2(u0, u1);
    __syncthreads();

    if (t < 64) {
        float2 a = up[0][t], b = up[1][t], d = up[2][t], e = up[3][t];
        *(float2*)&g_u[c * 512 + ob * 128 + t * 2] =
            make_float2(scale * (a.x + b.x + d.x + e.x),
                        scale * (a.y + b.y + d.y + e.y));
    }

    if (ob == 0) {
        float p = bias[t] * csm[t] + bias[t + 256] * csm[t + 256];
#pragma unroll
        for (int off = 16; off > 0; off >>= 1)
            p += __shfl_xor_sync(0xffffffffu, p, off);
        if ((t & 31) == 0) red2[t >> 5] = p;
        __syncthreads();
        if (t == 0) {
            float pp = 0.f;
#pragma unroll
            for (int k = 0; k < 8; k++) pp += red2[k];
            g_bc[c] = scale * pp;
        }
    }
}

// ============================================================================
// Final output: out[c,:] = scale_c * craw[c,:]
// ============================================================================
__global__ void __launch_bounds__(256) out_kernel(float* __restrict__ out) {
    const int c = blockIdx.x, t = threadIdx.x;
    __shared__ float scsh;
    if (t == 0) {
        float sq = g_sqp[c * 4] + g_sqp[c * 4 + 1] + g_sqp[c * 4 + 2] + g_sqp[c * 4 + 3];
        scsh = (sq / (1.f + sq)) * rsqrtf(sq + 1e-7f);
    }
    __syncthreads();
    out[c * 512 + t]       = scsh * g_craw[c * 512 + t];
    out[c * 512 + t + 256] = scsh * g_craw[c * 512 + t + 256];
}

// ============================================================================
extern "C" void kernel_launch(void* const* d_in, const int* in_sizes, int n_in,
                              void* d_out, int out_size) {
    const float* x    = (const float*)d_in[0];
    const float* W    = (const float*)d_in[1];
    const float* bias = (const float*)d_in[2];
    float* out = (float*)d_out;

    void* pb = nullptr; cudaGetSymbolAddress(&pb, g_b);
    cudaMemsetAsync(pb, 0, (size_t)M_ROWS * sizeof(float));

    convw_kernel<<<256, 256>>>(W);

    static bool attr_done = false;
    if (!attr_done) {
        cudaFuncSetAttribute(gemm_norms, cudaFuncAttributeMaxDynamicSharedMemorySize, GSM_TOTAL);
        cudaFuncSetAttribute(sweep_pass, cudaFuncAttributeMaxDynamicSharedMemorySize, SWEEP_SMEM);
        attr_done = true;
    }
    gemm_norms<<<dim3(4, 1024), 256, GSM_TOTAL>>>(x, bias);

    for (int it = 0; it < 3; ++it) {
        sweep_pass<<<dim3(NCHUNK, C_CAPS), 256, SWEEP_SMEM>>>(x, it > 0 ? 1 : 0);
        reduce_y<<<C_CAPS, 256>>>();
        cmat_kernel<<<dim3(4, C_CAPS), 256>>>(W, bias);
        if (it < 2) ustep_kernel<<<dim3(4, C_CAPS), 256>>>(W, bias);
        else        out_kernel<<<C_CAPS, 256>>>(out);
    }
}

// round 6
// speedup vs baseline: 1.8215x; 1.0042x over previous
#include <cuda_runtime.h>
#include <cuda_bf16.h>
#include <cstdint>

#define C_CAPS 64
#define S_DIM 2048
#define H_DIM 512
#define M_ROWS (C_CAPS * S_DIM)   // 131072
#define NCHUNK 16
#define CHUNK_S (S_DIM / NCHUNK)  // 128
#define RSTG 32
#define NSTG (CHUNK_S / RSTG)     // 4

// ---------------- device scratch ----------------
__device__ __align__(128) __nv_bfloat16 g_whi[(size_t)H_DIM * H_DIM];
__device__ __align__(128) __nv_bfloat16 g_wlo[(size_t)H_DIM * H_DIM];
__device__ float g_norms[4 * M_ROWS];
__device__ float g_b[M_ROWS];
__device__ float g_u[C_CAPS * H_DIM];
__device__ float g_bc[C_CAPS];
__device__ float g_Mp[C_CAPS * NCHUNK];
__device__ float g_Zp[C_CAPS * NCHUNK];
__device__ float g_Wp[C_CAPS * NCHUNK];
__device__ float g_Vp[(size_t)C_CAPS * NCHUNK * H_DIM];
__device__ float g_y[C_CAPS * H_DIM];
__device__ float g_wts[C_CAPS];
__device__ float g_craw[C_CAPS * H_DIM];
__device__ float g_sqp[C_CAPS * 4];

// ---------------- helpers ----------------
__device__ __forceinline__ uint32_t smem_u32(const void* p) {
    uint32_t a;
    asm("{ .reg .u64 t; cvta.to.shared.u64 t, %1; cvt.u32.u64 %0, t; }" : "=r"(a) : "l"(p));
    return a;
}
__device__ __forceinline__ void ldsm4(uint32_t* r, uint32_t addr) {
    asm volatile("ldmatrix.sync.aligned.m8n8.x4.shared.b16 {%0,%1,%2,%3}, [%4];"
        : "=r"(r[0]), "=r"(r[1]), "=r"(r[2]), "=r"(r[3]) : "r"(addr));
}
__device__ __forceinline__ void mma16816(float* d, const uint32_t* a, const uint32_t* b) {
    asm volatile("mma.sync.aligned.m16n8k16.row.col.f32.bf16.bf16.f32 "
        "{%0,%1,%2,%3}, {%4,%5,%6,%7}, {%8,%9}, {%0,%1,%2,%3};"
        : "+f"(d[0]), "+f"(d[1]), "+f"(d[2]), "+f"(d[3])
        : "r"(a[0]), "r"(a[1]), "r"(a[2]), "r"(a[3]), "r"(b[0]), "r"(b[1]));
}
__device__ __forceinline__ void sts128(uint32_t addr, uint4 v) {
    asm volatile("st.shared.v4.b32 [%0], {%1,%2,%3,%4};"
        :: "r"(addr), "r"(v.x), "r"(v.y), "r"(v.z), "r"(v.w) : "memory");
}
#define CP_ASYNC16(dst, src) \
    asm volatile("cp.async.cg.shared.global [%0], [%1], 16;" :: "r"(dst), "l"(src) : "memory")
#define CP_COMMIT() asm volatile("cp.async.commit_group;" ::: "memory")
#define CP_WAIT(n)  asm volatile("cp.async.wait_group %0;" :: "n"(n) : "memory")

__device__ __forceinline__ uint32_t packhi2(float x, float y) {
    __nv_bfloat16 hx = __float2bfloat16_rn(x);
    __nv_bfloat16 hy = __float2bfloat16_rn(y);
    return (uint32_t)__bfloat16_as_ushort(hy) << 16 | __bfloat16_as_ushort(hx);
}
__device__ __forceinline__ uint32_t tswz(uint32_t row, uint32_t kc) {
    return row * 64u + ((kc ^ ((row >> 1) & 3u)) << 4);
}

// ============================================================================
// convw: W fp32 -> pre-swizzled bf16 hi/lo tiles (8KB blocks [128 x 32]).
// ============================================================================
__global__ void convw_kernel(const float* __restrict__ W) {
    int g = blockIdx.x * 256 + threadIdx.x;
    int n = g >> 7, ch = g & 127;
    int kt = ch >> 3, kc = (ch >> 1) & 3, half = ch & 1;
    int bn = n >> 7, nrow = n & 127;
    float4 v = *(const float4*)&W[(size_t)n * 512 + ch * 4];
    __nv_bfloat16 h0 = __float2bfloat16_rn(v.x), h1 = __float2bfloat16_rn(v.y);
    __nv_bfloat16 h2 = __float2bfloat16_rn(v.z), h3 = __float2bfloat16_rn(v.w);
    uint2 hi, lo;
    hi.x = (uint32_t)__bfloat16_as_ushort(h1) << 16 | __bfloat16_as_ushort(h0);
    hi.y = (uint32_t)__bfloat16_as_ushort(h3) << 16 | __bfloat16_as_ushort(h2);
    lo.x = packhi2(v.x - __bfloat162float(h0), v.y - __bfloat162float(h1));
    lo.y = packhi2(v.z - __bfloat162float(h2), v.w - __bfloat162float(h3));
    size_t dst = ((size_t)(bn * 16 + kt) << 13) + tswz(nrow, kc) + half * 8;
    *(uint2*)((char*)g_whi + dst) = hi;
    *(uint2*)((char*)g_wlo + dst) = lo;
}

// ============================================================================
// GEMM (norms only): 2-product split xh*(Wh+Wl). Tile 128x128, BK=32, 8 warps.
// ============================================================================
#define GSM_STAGE 24576
#define GSM_TOTAL (2 * GSM_STAGE + 512)

__device__ __forceinline__ void issueB(uint32_t stg, int bn, int kt, int t) {
    size_t tile = (size_t)(bn * 16 + kt) << 13;
    const char* sh = (const char*)g_whi + tile + t * 32;
    const char* sl = (const char*)g_wlo + tile + t * 32;
    CP_ASYNC16(stg + 8192 + t * 32, sh);
    CP_ASYNC16(stg + 8192 + t * 32 + 16, sh + 16);
    CP_ASYNC16(stg + 16384 + t * 32, sl);
    CP_ASYNC16(stg + 16384 + t * 32 + 16, sl + 16);
}

__global__ void __launch_bounds__(256, 1) gemm_norms(
    const float* __restrict__ x, const float* __restrict__ bias)
{
    extern __shared__ __align__(1024) char smem[];
    const uint32_t sb = smem_u32(smem);

    const int t = threadIdx.x, l = t & 31, wid = t >> 5;
    const int wm = wid & 3, wn = wid >> 2;
    const int bn = blockIdx.x, mtile = blockIdx.y;

    const int c0row = t >> 2, ckc = t & 3;
    const float* ag0 = x + ((size_t)mtile * 128 + c0row) * 512 + ckc * 8;
    const float* ag1 = x + ((size_t)mtile * 128 + c0row + 64) * 512 + ckc * 8;
    const uint32_t so0 = tswz(c0row, ckc);
    const uint32_t so1 = tswz(c0row + 64, ckc);

    uint32_t aoffA[2][2], aoffB[4][2];
#pragma unroll
    for (int mt = 0; mt < 2; mt++)
#pragma unroll
        for (int ks = 0; ks < 2; ks++) {
            uint32_t m = wm * 32 + mt * 16 + ((l >> 3) & 1) * 8 + (l & 7);
            aoffA[mt][ks] = tswz(m, ks * 2 + (l >> 4));
        }
#pragma unroll
    for (int nt2 = 0; nt2 < 4; nt2++)
#pragma unroll
        for (int ks = 0; ks < 2; ks++) {
            uint32_t n = wn * 64 + nt2 * 16 + ((l >> 4) & 1) * 8 + (l & 7);
            aoffB[nt2][ks] = tswz(n, ks * 2 + ((l >> 3) & 1));
        }

    float acc[2][8][4];
#pragma unroll
    for (int mt = 0; mt < 2; mt++)
#pragma unroll
        for (int nt = 0; nt < 8; nt++)
#pragma unroll
            for (int k = 0; k < 4; k++) acc[mt][nt][k] = 0.f;

    issueB(sb, bn, 0, t);
    CP_COMMIT();
    float4 pa[2][2];
    pa[0][0] = *(const float4*)(ag0); pa[0][1] = *(const float4*)(ag0 + 4);
    pa[1][0] = *(const float4*)(ag1); pa[1][1] = *(const float4*)(ag1 + 4);

    for (int kt = 0; kt < 16; kt++) {
        const uint32_t stg = sb + (kt & 1) * GSM_STAGE;
        {
            uint4 h0, h1;
            h0.x = packhi2(pa[0][0].x, pa[0][0].y); h0.y = packhi2(pa[0][0].z, pa[0][0].w);
            h0.z = packhi2(pa[0][1].x, pa[0][1].y); h0.w = packhi2(pa[0][1].z, pa[0][1].w);
            h1.x = packhi2(pa[1][0].x, pa[1][0].y); h1.y = packhi2(pa[1][0].z, pa[1][0].w);
            h1.z = packhi2(pa[1][1].x, pa[1][1].y); h1.w = packhi2(pa[1][1].z, pa[1][1].w);
            sts128(stg + so0, h0);
            sts128(stg + so1, h1);
        }
        if (kt < 15) {
            issueB(sb + ((kt + 1) & 1) * GSM_STAGE, bn, kt + 1, t);
            CP_COMMIT();
            CP_WAIT(1);
        } else {
            CP_WAIT(0);
        }
        __syncthreads();

        if (kt < 15) {
            int ko = (kt + 1) * 32;
            pa[0][0] = *(const float4*)(ag0 + ko); pa[0][1] = *(const float4*)(ag0 + ko + 4);
            pa[1][0] = *(const float4*)(ag1 + ko); pa[1][1] = *(const float4*)(ag1 + ko + 4);
        }

#pragma unroll
        for (int ks = 0; ks < 2; ks++) {
            uint32_t ah[2][4], bh[4][4], bl[4][4];
#pragma unroll
            for (int mt = 0; mt < 2; mt++) ldsm4(ah[mt], stg + aoffA[mt][ks]);
#pragma unroll
            for (int nt2 = 0; nt2 < 4; nt2++) {
                ldsm4(bh[nt2], stg + 8192 + aoffB[nt2][ks]);
                ldsm4(bl[nt2], stg + 16384 + aoffB[nt2][ks]);
            }
#pragma unroll
            for (int mt = 0; mt < 2; mt++)
#pragma unroll
                for (int nt = 0; nt < 8; nt++) {
                    mma16816(acc[mt][nt], ah[mt], &bh[nt >> 1][(nt & 1) * 2]);
                    mma16816(acc[mt][nt], ah[mt], &bl[nt >> 1][(nt & 1) * 2]);
                }
        }
        __syncthreads();
    }

    float* norm_sm = (float*)(smem + 2 * GSM_STAGE);
    if (t < 128) norm_sm[t] = 0.f;
    __syncthreads();

    float2 bias2[8];
#pragma unroll
    for (int nt = 0; nt < 8; nt++)
        bias2[nt] = *(const float2*)&bias[bn * 128 + wn * 64 + nt * 8 + (l & 3) * 2];

#pragma unroll
    for (int mt = 0; mt < 2; mt++)
#pragma unroll
        for (int half = 0; half < 2; half++) {
            int r = wm * 32 + mt * 16 + (l >> 2) + half * 8;
            float ss = 0.f;
#pragma unroll
            for (int nt = 0; nt < 8; nt++) {
                float vx = acc[mt][nt][half * 2]     + bias2[nt].x;
                float vy = acc[mt][nt][half * 2 + 1] + bias2[nt].y;
                ss += vx * vx + vy * vy;
            }
            ss += __shfl_xor_sync(0xffffffffu, ss, 1);
            ss += __shfl_xor_sync(0xffffffffu, ss, 2);
            if ((l & 3) == 0) atomicAdd(&norm_sm[r], ss);
        }
    __syncthreads();
    if (t < 128)
        g_norms[(size_t)bn * M_ROWS + (size_t)mtile * 128 + t] = norm_sm[t];
}

// ============================================================================
// Sweep: cp.async double-buffered, 32-row stages. Chunk partials out.
// Dynamic smem: 2 x 32 x 512 floats = 128 KB.
// ============================================================================
#define SWEEP_SMEM (2 * RSTG * 512 * 4)

__global__ void __launch_bounds__(256) sweep_pass(const float* __restrict__ x, int do_dot) {
    extern __shared__ __align__(16) float tiles[];
    __shared__ float usm[512];
    __shared__ float bst[RSTG], sst[RSTG], wst[RSTG];
    __shared__ float runMs, Zsh, Wsh, fsh, bcs;

    const int c = blockIdx.y, chunk = blockIdx.x;
    const int t = threadIdx.x, wid = t >> 5, lane = t & 31;

    usm[t]       = do_dot ? g_u[c * 512 + t] : 0.f;
    usm[t + 256] = do_dot ? g_u[c * 512 + t + 256] : 0.f;
    if (t == 0) { runMs = -1e30f; Zsh = 0.f; Wsh = 0.f; bcs = do_dot ? g_bc[c] : 0.f; }

    const size_t rowbase = (size_t)c * S_DIM + (size_t)chunk * CHUNK_S;
    float ax = 0.f, ay = 0.f;

    // prologue: stage 0
    {
        const float* src = x + rowbase * 512;
        uint32_t dst = smem_u32(tiles);
#pragma unroll
        for (int i = 0; i < 16; i++) {
            int idx = t + 256 * i;
            CP_ASYNC16(dst + idx * 16, src + idx * 4);
        }
        CP_COMMIT();
    }

    for (int st = 0; st < NSTG; st++) {
        CP_WAIT(0);
        __syncthreads();
        float* tile = tiles + (st & 1) * (RSTG * 512);

        if (st < NSTG - 1) {
            const float* src = x + (rowbase + (size_t)(st + 1) * RSTG) * 512;
            uint32_t dst = smem_u32(tiles + ((st + 1) & 1) * (RSTG * 512));
#pragma unroll
            for (int i = 0; i < 16; i++) {
                int idx = t + 256 * i;
                CP_ASYNC16(dst + idx * 16, src + idx * 4);
            }
            CP_COMMIT();
        }

        // dots: each warp handles 4 rows
#pragma unroll
        for (int rr = 0; rr < 4; rr++) {
            int rl = wid * 4 + rr;
            float dot = 0.f;
            if (do_dot) {
                const float4* tr = (const float4*)(tile + rl * 512);
#pragma unroll
                for (int j = 0; j < 4; j++) {
                    float4 v = tr[lane + 32 * j];
                    float4 cv = *(const float4*)&usm[(lane + 32 * j) * 4];
                    dot += v.x * cv.x + v.y * cv.y + v.z * cv.z + v.w * cv.w;
                }
#pragma unroll
                for (int off = 16; off > 0; off >>= 1)
                    dot += __shfl_xor_sync(0xffffffffu, dot, off);
            }
            if (lane == 0) {
                size_t row = rowbase + st * RSTG + rl;
                float sq = g_norms[row] + g_norms[M_ROWS + row]
                         + g_norms[2 * M_ROWS + row] + g_norms[3 * M_ROWS + row];
                float scale = (sq / (1.f + sq)) * rsqrtf(sq + 1e-7f);
                float bv;
                if (do_dot) {
                    bv = g_b[row] + scale * (dot + bcs);
                    g_b[row] = bv;
                } else {
                    bv = 0.f;
                }
                bst[rl] = bv;
                sst[rl] = scale;
            }
        }
        __syncthreads();

        if (t < 32) {
            float v = bst[lane];
            float m = v;
#pragma unroll
            for (int off = 16; off > 0; off >>= 1)
                m = fmaxf(m, __shfl_xor_sync(0xffffffffu, m, off));
            float rm = runMs;
            float nm = fmaxf(rm, m);
            float w = __expf(v - nm);
            float zst = w;
#pragma unroll
            for (int off = 16; off > 0; off >>= 1)
                zst += __shfl_xor_sync(0xffffffffu, zst, off);
            float wsv = w * sst[lane];
            float wss = wsv;
#pragma unroll
            for (int off = 16; off > 0; off >>= 1)
                wss += __shfl_xor_sync(0xffffffffu, wss, off);
            wst[lane] = wsv;
            if (lane == 0) {
                float f = __expf(rm - nm);
                fsh = f;
                Zsh = Zsh * f + zst;
                Wsh = Wsh * f + wss;
                runMs = nm;
            }
        }
        __syncthreads();

        float f = fsh;
        ax *= f; ay *= f;
#pragma unroll
        for (int r = 0; r < RSTG; r++) {
            float w = wst[r];
            float2 v = *(const float2*)(tile + r * 512 + 2 * t);
            ax += w * v.x;
            ay += w * v.y;
        }
        // no trailing sync: top-of-loop syncthreads protects buffers
    }

    int pc = c * NCHUNK + chunk;
    *(float2*)&g_Vp[(size_t)pc * 512 + 2 * t] = make_float2(ax, ay);
    if (t == 0) { g_Mp[pc] = runMs; g_Zp[pc] = Zsh; g_Wp[pc] = Wsh; }
}

// ============================================================================
// K1: reduce chunk partials -> y[c,512], wts[c]
// ============================================================================
__global__ void __launch_bounds__(256) reduce_y() {
    const int c = blockIdx.x, t = threadIdx.x;
    __shared__ float sk[NCHUNK];
    __shared__ float Zs;

    if (t == 0) {
        float M = g_Mp[c * NCHUNK];
#pragma unroll
        for (int k = 1; k < NCHUNK; k++) M = fmaxf(M, g_Mp[c * NCHUNK + k]);
        float Z = 0.f, Wt = 0.f;
#pragma unroll
        for (int k = 0; k < NCHUNK; k++) {
            float e = __expf(g_Mp[c * NCHUNK + k] - M);
            sk[k] = e;
            Z  += g_Zp[c * NCHUNK + k] * e;
            Wt += g_Wp[c * NCHUNK + k] * e;
        }
        Zs = Z;
        g_wts[c] = Wt / Z;
    }
    __syncthreads();

    float w0 = 0.f, w1 = 0.f;
#pragma unroll
    for (int k = 0; k < NCHUNK; k++) {
        float e = sk[k];
        float2 v = *(const float2*)&g_Vp[((size_t)(c * NCHUNK + k)) * 512 + 2 * t];
        w0 += e * v.x;
        w1 += e * v.y;
    }
    float invZ = 1.f / Zs;
    *(float2*)&g_y[c * 512 + 2 * t] = make_float2(w0 * invZ, w1 * invZ);
}

// ============================================================================
// K2: craw[c,o] = y_c . W_o + bias_o * wts_c ; per-block partial sumsq.
// grid (4, 64): block = (output block ob, capsule c). Warp per 16 outputs.
// ============================================================================
__global__ void __launch_bounds__(256) cmat_kernel(
    const float* __restrict__ W, const float* __restrict__ bias)
{
    const int ob = blockIdx.x, c = blockIdx.y;
    const int t = threadIdx.x, wid = t >> 5, lane = t & 31;
    __shared__ float ysm[512];
    __shared__ float ssp[8];

    ysm[t]       = g_y[c * 512 + t];
    ysm[t + 256] = g_y[c * 512 + t + 256];
    __syncthreads();

    const float Wts = g_wts[c];
    float ss = 0.f;
#pragma unroll
    for (int i = 0; i < 16; i++) {
        int o = ob * 128 + wid * 16 + i;
        const float4* wr = (const float4*)(W + (size_t)o * 512);
        float d = 0.f;
#pragma unroll
        for (int g = 0; g < 4; g++) {
            float4 a = wr[lane + 32 * g];
            float4 b = *(const float4*)&ysm[(lane + 32 * g) * 4];
            d += a.x * b.x + a.y * b.y + a.z * b.z + a.w * b.w;
        }
#pragma unroll
        for (int off = 16; off > 0; off >>= 1)
            d += __shfl_xor_sync(0xffffffffu, d, off);
        if (lane == 0) {
            float cr = d + bias[o] * Wts;
            g_craw[c * 512 + o] = cr;
            ss += cr * cr;
        }
    }
    if (lane == 0) ssp[wid] = ss;
    __syncthreads();
    if (t == 0) {
        float s = 0.f;
#pragma unroll
        for (int k = 0; k < 8; k++) s += ssp[k];
        g_sqp[c * 4 + ob] = s;
    }
}

// ============================================================================
// K3: scale from sumsq; u[c,:] = scale * W^T craw_c ; bc = scale*(bias.craw).
// grid (4, 64): block = (h block ob, capsule c). o-loop split 4 ways.
// ============================================================================
__global__ void __launch_bounds__(256) ustep_kernel(
    const float* __restrict__ W, const float* __restrict__ bias)
{
    const int ob = blockIdx.x, c = blockIdx.y;
    const int t = threadIdx.x;
    const int og = t >> 6, cp = t & 63;

    __shared__ float csm[512];
    __shared__ float2 up[4][64];
    __shared__ float scsh;
    __shared__ float red2[8];

    csm[t]       = g_craw[c * 512 + t];
    csm[t + 256] = g_craw[c * 512 + t + 256];
    if (t == 0) {
        float sq = g_sqp[c * 4] + g_sqp[c * 4 + 1] + g_sqp[c * 4 + 2] + g_sqp[c * 4 + 3];
        scsh = (sq / (1.f + sq)) * rsqrtf(sq + 1e-7f);
    }
    __syncthreads();
    const float scale = scsh;

    float u0 = 0.f, u1 = 0.f;
    const float* wp = W + (size_t)(og * 128) * 512 + ob * 128 + cp * 2;
#pragma unroll 8
    for (int o = 0; o < 128; o++) {
        float co = csm[og * 128 + o];
        float2 wv = *(const float2*)(wp + (size_t)o * 512);
        u0 += co * wv.x;
        u1 += co * wv.y;
    }
    up[og][cp] = make_float2(u0, u1);
    __syncthreads();

    if (t < 64) {
        float2 a = up[0][t], b = up[1][t], d = up[2][t], e = up[3][t];
        *(float2*)&g_u[c * 512 + ob * 128 + t * 2] =
            make_float2(scale * (a.x + b.x + d.x + e.x),
                        scale * (a.y + b.y + d.y + e.y));
    }

    if (ob == 0) {
        float p = bias[t] * csm[t] + bias[t + 256] * csm[t + 256];
#pragma unroll
        for (int off = 16; off > 0; off >>= 1)
            p += __shfl_xor_sync(0xffffffffu, p, off);
        if ((t & 31) == 0) red2[t >> 5] = p;
        __syncthreads();
        if (t == 0) {
            float pp = 0.f;
#pragma unroll
            for (int k = 0; k < 8; k++) pp += red2[k];
            g_bc[c] = scale * pp;
        }
    }
}

// ============================================================================
// Final output: out[c,:] = scale_c * craw[c,:]
// ============================================================================
__global__ void __launch_bounds__(256) out_kernel(float* __restrict__ out) {
    const int c = blockIdx.x, t = threadIdx.x;
    __shared__ float scsh;
    if (t == 0) {
        float sq = g_sqp[c * 4] + g_sqp[c * 4 + 1] + g_sqp[c * 4 + 2] + g_sqp[c * 4 + 3];
        scsh = (sq / (1.f + sq)) * rsqrtf(sq + 1e-7f);
    }
    __syncthreads();
    out[c * 512 + t]       = scsh * g_craw[c * 512 + t];
    out[c * 512 + t + 256] = scsh * g_craw[c * 512 + t + 256];
}

// ============================================================================
extern "C" void kernel_launch(void* const* d_in, const int* in_sizes, int n_in,
                              void* d_out, int out_size) {
    const float* x    = (const float*)d_in[0];
    const float* W    = (const float*)d_in[1];
    const float* bias = (const float*)d_in[2];
    float* out = (float*)d_out;

    void* pb = nullptr; cudaGetSymbolAddress(&pb, g_b);
    cudaMemsetAsync(pb, 0, (size_t)M_ROWS * sizeof(float));

    convw_kernel<<<256, 256>>>(W);

    static bool attr_done = false;
    if (!attr_done) {
        cudaFuncSetAttribute(gemm_norms, cudaFuncAttributeMaxDynamicSharedMemorySize, GSM_TOTAL);
        cudaFuncSetAttribute(sweep_pass, cudaFuncAttributeMaxDynamicSharedMemorySize, SWEEP_SMEM);
        attr_done = true;
    }
    gemm_norms<<<dim3(4, 1024), 256, GSM_TOTAL>>>(x, bias);

    for (int it = 0; it < 3; ++it) {
        sweep_pass<<<dim3(NCHUNK, C_CAPS), 256, SWEEP_SMEM>>>(x, it > 0 ? 1 : 0);
        reduce_y<<<C_CAPS, 256>>>();
        cmat_kernel<<<dim3(4, C_CAPS), 256>>>(W, bias);
        if (it < 2) ustep_kernel<<<dim3(4, C_CAPS), 256>>>(W, bias);
        else        out_kernel<<<C_CAPS, 256>>>(out);
    }
}

// round 7
// speedup vs baseline: 2.8101x; 1.5427x over previous
#include <cuda_runtime.h>
#include <cuda_bf16.h>
#include <cstdint>

#define C_CAPS 64
#define S_DIM 2048
#define H_DIM 512
#define M_ROWS (C_CAPS * S_DIM)   // 131072
#define NCHUNK 16
#define CHUNK_S (S_DIM / NCHUNK)  // 128
#define RSTG 16
#define NSTG (CHUNK_S / RSTG)     // 8
#define SLOTS 3

// ---------------- device scratch ----------------
__device__ __align__(128) __nv_bfloat16 g_whi[(size_t)H_DIM * H_DIM];
__device__ float g_norms[4 * M_ROWS];
__device__ float g_b[M_ROWS];
__device__ float g_u[C_CAPS * H_DIM];
__device__ float g_bc[C_CAPS];
__device__ float g_Mp[C_CAPS * NCHUNK];
__device__ float g_Zp[C_CAPS * NCHUNK];
__device__ float g_Wp[C_CAPS * NCHUNK];
__device__ float g_Vp[(size_t)C_CAPS * NCHUNK * H_DIM];
__device__ float g_craw[C_CAPS * H_DIM];
__device__ float g_sqp[C_CAPS * 4];

// ---------------- helpers ----------------
__device__ __forceinline__ uint32_t smem_u32(const void* p) {
    uint32_t a;
    asm("{ .reg .u64 t; cvta.to.shared.u64 t, %1; cvt.u32.u64 %0, t; }" : "=r"(a) : "l"(p));
    return a;
}
__device__ __forceinline__ void ldsm4(uint32_t* r, uint32_t addr) {
    asm volatile("ldmatrix.sync.aligned.m8n8.x4.shared.b16 {%0,%1,%2,%3}, [%4];"
        : "=r"(r[0]), "=r"(r[1]), "=r"(r[2]), "=r"(r[3]) : "r"(addr));
}
__device__ __forceinline__ void mma16816(float* d, const uint32_t* a, const uint32_t* b) {
    asm volatile("mma.sync.aligned.m16n8k16.row.col.f32.bf16.bf16.f32 "
        "{%0,%1,%2,%3}, {%4,%5,%6,%7}, {%8,%9}, {%0,%1,%2,%3};"
        : "+f"(d[0]), "+f"(d[1]), "+f"(d[2]), "+f"(d[3])
        : "r"(a[0]), "r"(a[1]), "r"(a[2]), "r"(a[3]), "r"(b[0]), "r"(b[1]));
}
__device__ __forceinline__ void sts128(uint32_t addr, uint4 v) {
    asm volatile("st.shared.v4.b32 [%0], {%1,%2,%3,%4};"
        :: "r"(addr), "r"(v.x), "r"(v.y), "r"(v.z), "r"(v.w) : "memory");
}
#define CP_ASYNC16(dst, src) \
    asm volatile("cp.async.cg.shared.global [%0], [%1], 16;" :: "r"(dst), "l"(src) : "memory")
#define CP_COMMIT() asm volatile("cp.async.commit_group;" ::: "memory")
#define CP_WAIT(n)  asm volatile("cp.async.wait_group %0;" :: "n"(n) : "memory")

__device__ __forceinline__ uint32_t packhi2(float x, float y) {
    __nv_bfloat16 hx = __float2bfloat16_rn(x);
    __nv_bfloat16 hy = __float2bfloat16_rn(y);
    return (uint32_t)__bfloat16_as_ushort(hy) << 16 | __bfloat16_as_ushort(hx);
}
__device__ __forceinline__ uint32_t tswz(uint32_t row, uint32_t kc) {
    return row * 64u + ((kc ^ ((row >> 1) & 3u)) << 4);
}

// ============================================================================
// convw: W fp32 -> pre-swizzled bf16 tiles (8KB blocks [128 rows x 32 k]).
// ============================================================================
__global__ void convw_kernel(const float* __restrict__ W) {
    int g = blockIdx.x * 256 + threadIdx.x;
    int n = g >> 7, ch = g & 127;
    int kt = ch >> 3, kc = (ch >> 1) & 3, half = ch & 1;
    int bn = n >> 7, nrow = n & 127;
    float4 v = *(const float4*)&W[(size_t)n * 512 + ch * 4];
    uint2 hi;
    hi.x = packhi2(v.x, v.y);
    hi.y = packhi2(v.z, v.w);
    size_t dst = ((size_t)(bn * 16 + kt) << 13) + tswz(nrow, kc) + half * 8;
    *(uint2*)((char*)g_whi + dst) = hi;
}

// ============================================================================
// GEMM (norms only): single-product bf16 xh*Wh. Tile 128x128, BK=32, 8 warps.
// Stage = Ah 8K | Bh 8K, double-buffered. B via cp.async from pre-swizzled W.
// ============================================================================
#define GSM_STAGE 16384
#define GSM_TOTAL (2 * GSM_STAGE + 512)

__device__ __forceinline__ void issueB(uint32_t stg, int bn, int kt, int t) {
    size_t tile = (size_t)(bn * 16 + kt) << 13;
    const char* sh = (const char*)g_whi + tile + t * 32;
    CP_ASYNC16(stg + 8192 + t * 32, sh);
    CP_ASYNC16(stg + 8192 + t * 32 + 16, sh + 16);
}

__global__ void __launch_bounds__(256, 2) gemm_norms(
    const float* __restrict__ x, const float* __restrict__ bias)
{
    extern __shared__ __align__(1024) char smem[];
    const uint32_t sb = smem_u32(smem);

    const int t = threadIdx.x, l = t & 31, wid = t >> 5;
    const int wm = wid & 3, wn = wid >> 2;
    const int bn = blockIdx.x, mtile = blockIdx.y;

    const int c0row = t >> 2, ckc = t & 3;
    const float* ag0 = x + ((size_t)mtile * 128 + c0row) * 512 + ckc * 8;
    const float* ag1 = x + ((size_t)mtile * 128 + c0row + 64) * 512 + ckc * 8;
    const uint32_t so0 = tswz(c0row, ckc);
    const uint32_t so1 = tswz(c0row + 64, ckc);

    uint32_t aoffA[2][2], aoffB[4][2];
#pragma unroll
    for (int mt = 0; mt < 2; mt++)
#pragma unroll
        for (int ks = 0; ks < 2; ks++) {
            uint32_t m = wm * 32 + mt * 16 + ((l >> 3) & 1) * 8 + (l & 7);
            aoffA[mt][ks] = tswz(m, ks * 2 + (l >> 4));
        }
#pragma unroll
    for (int nt2 = 0; nt2 < 4; nt2++)
#pragma unroll
        for (int ks = 0; ks < 2; ks++) {
            uint32_t n = wn * 64 + nt2 * 16 + ((l >> 4) & 1) * 8 + (l & 7);
            aoffB[nt2][ks] = tswz(n, ks * 2 + ((l >> 3) & 1));
        }

    float acc[2][8][4];
#pragma unroll
    for (int mt = 0; mt < 2; mt++)
#pragma unroll
        for (int nt = 0; nt < 8; nt++)
#pragma unroll
            for (int k = 0; k < 4; k++) acc[mt][nt][k] = 0.f;

    issueB(sb, bn, 0, t);
    CP_COMMIT();
    float4 pa[2][2];
    pa[0][0] = *(const float4*)(ag0); pa[0][1] = *(const float4*)(ag0 + 4);
    pa[1][0] = *(const float4*)(ag1); pa[1][1] = *(const float4*)(ag1 + 4);

    for (int kt = 0; kt < 16; kt++) {
        const uint32_t stg = sb + (kt & 1) * GSM_STAGE;
        {
            uint4 h0, h1;
            h0.x = packhi2(pa[0][0].x, pa[0][0].y); h0.y = packhi2(pa[0][0].z, pa[0][0].w);
            h0.z = packhi2(pa[0][1].x, pa[0][1].y); h0.w = packhi2(pa[0][1].z, pa[0][1].w);
            h1.x = packhi2(pa[1][0].x, pa[1][0].y); h1.y = packhi2(pa[1][0].z, pa[1][0].w);
            h1.z = packhi2(pa[1][1].x, pa[1][1].y); h1.w = packhi2(pa[1][1].z, pa[1][1].w);
            sts128(stg + so0, h0);
            sts128(stg + so1, h1);
        }
        if (kt < 15) {
            issueB(sb + ((kt + 1) & 1) * GSM_STAGE, bn, kt + 1, t);
            CP_COMMIT();
            CP_WAIT(1);
        } else {
            CP_WAIT(0);
        }
        __syncthreads();

        if (kt < 15) {
            int ko = (kt + 1) * 32;
            pa[0][0] = *(const float4*)(ag0 + ko); pa[0][1] = *(const float4*)(ag0 + ko + 4);
            pa[1][0] = *(const float4*)(ag1 + ko); pa[1][1] = *(const float4*)(ag1 + ko + 4);
        }

#pragma unroll
        for (int ks = 0; ks < 2; ks++) {
            uint32_t ah[2][4], bh[4][4];
#pragma unroll
            for (int mt = 0; mt < 2; mt++) ldsm4(ah[mt], stg + aoffA[mt][ks]);
#pragma unroll
            for (int nt2 = 0; nt2 < 4; nt2++) ldsm4(bh[nt2], stg + 8192 + aoffB[nt2][ks]);
#pragma unroll
            for (int mt = 0; mt < 2; mt++)
#pragma unroll
                for (int nt = 0; nt < 8; nt++)
                    mma16816(acc[mt][nt], ah[mt], &bh[nt >> 1][(nt & 1) * 2]);
        }
        __syncthreads();
    }

    float* norm_sm = (float*)(smem + 2 * GSM_STAGE);
    if (t < 128) norm_sm[t] = 0.f;
    __syncthreads();

    float2 bias2[8];
#pragma unroll
    for (int nt = 0; nt < 8; nt++)
        bias2[nt] = *(const float2*)&bias[bn * 128 + wn * 64 + nt * 8 + (l & 3) * 2];

#pragma unroll
    for (int mt = 0; mt < 2; mt++)
#pragma unroll
        for (int half = 0; half < 2; half++) {
            int r = wm * 32 + mt * 16 + (l >> 2) + half * 8;
            float ss = 0.f;
#pragma unroll
            for (int nt = 0; nt < 8; nt++) {
                float vx = acc[mt][nt][half * 2]     + bias2[nt].x;
                float vy = acc[mt][nt][half * 2 + 1] + bias2[nt].y;
                ss += vx * vx + vy * vy;
            }
            ss += __shfl_xor_sync(0xffffffffu, ss, 1);
            ss += __shfl_xor_sync(0xffffffffu, ss, 2);
            if ((l & 3) == 0) atomicAdd(&norm_sm[r], ss);
        }
    __syncthreads();
    if (t < 128)
        g_norms[(size_t)bn * M_ROWS + (size_t)mtile * 128 + t] = norm_sm[t];
}

// ============================================================================
// Sweep: 3-slot cp.async ring, 16-row stages (96KB dynamic smem, 2 CTAs/SM).
// ============================================================================
#define SWEEP_SMEM (SLOTS * RSTG * 512 * 4)

__device__ __forceinline__ void sweep_issue(const float* src, float* slot, int t) {
    uint32_t dst = smem_u32(slot);
#pragma unroll
    for (int i = 0; i < 8; i++) {
        int idx = t + 256 * i;
        CP_ASYNC16(dst + idx * 16, src + idx * 4);
    }
    CP_COMMIT();
}

__global__ void __launch_bounds__(256, 2) sweep_pass(const float* __restrict__ x, int do_dot) {
    extern __shared__ __align__(16) float tiles[];
    __shared__ float usm[512];
    __shared__ float bst[RSTG], sst[RSTG], wst[RSTG];
    __shared__ float runMs, Zsh, Wsh, fsh, bcs;

    const int c = blockIdx.y, chunk = blockIdx.x;
    const int t = threadIdx.x, wid = t >> 5, lane = t & 31;

    usm[t]       = do_dot ? g_u[c * 512 + t] : 0.f;
    usm[t + 256] = do_dot ? g_u[c * 512 + t + 256] : 0.f;
    if (t == 0) { runMs = -1e30f; Zsh = 0.f; Wsh = 0.f; bcs = do_dot ? g_bc[c] : 0.f; }

    const size_t rowbase = (size_t)c * S_DIM + (size_t)chunk * CHUNK_S;
    float ax = 0.f, ay = 0.f;

    sweep_issue(x + rowbase * 512, tiles, t);
    sweep_issue(x + (rowbase + RSTG) * 512, tiles + RSTG * 512, t);

    for (int st = 0; st < NSTG; st++) {
        if (st < NSTG - 1) { CP_WAIT(1); } else { CP_WAIT(0); }
        __syncthreads();
        float* tile = tiles + (st % SLOTS) * (RSTG * 512);

        if (st + 2 < NSTG)
            sweep_issue(x + (rowbase + (size_t)(st + 2) * RSTG) * 512,
                        tiles + ((st + 2) % SLOTS) * (RSTG * 512), t);

        // dots: each warp handles 2 rows
#pragma unroll
        for (int rr = 0; rr < 2; rr++) {
            int rl = wid * 2 + rr;
            float dot = 0.f;
            if (do_dot) {
                const float4* tr = (const float4*)(tile + rl * 512);
#pragma unroll
                for (int j = 0; j < 4; j++) {
                    float4 v = tr[lane + 32 * j];
                    float4 cv = *(const float4*)&usm[(lane + 32 * j) * 4];
                    dot += v.x * cv.x + v.y * cv.y + v.z * cv.z + v.w * cv.w;
                }
#pragma unroll
                for (int off = 16; off > 0; off >>= 1)
                    dot += __shfl_xor_sync(0xffffffffu, dot, off);
            }
            if (lane == 0) {
                size_t row = rowbase + st * RSTG + rl;
                float sq = g_norms[row] + g_norms[M_ROWS + row]
                         + g_norms[2 * M_ROWS + row] + g_norms[3 * M_ROWS + row];
                float scale = (sq / (1.f + sq)) * rsqrtf(sq + 1e-7f);
                float bv;
                if (do_dot) {
                    bv = g_b[row] + scale * (dot + bcs);
                    g_b[row] = bv;
                } else {
                    bv = 0.f;
                }
                bst[rl] = bv;
                sst[rl] = scale;
            }
        }
        __syncthreads();

        if (t < 32) {
            float v = (lane < RSTG) ? bst[lane] : -1e30f;
            float m = v;
#pragma unroll
            for (int off = 16; off > 0; off >>= 1)
                m = fmaxf(m, __shfl_xor_sync(0xffffffffu, m, off));
            float rm = runMs;
            float nm = fmaxf(rm, m);
            float w = __expf(v - nm);
            float zst = w;
#pragma unroll
            for (int off = 16; off > 0; off >>= 1)
                zst += __shfl_xor_sync(0xffffffffu, zst, off);
            float wsv = (lane < RSTG) ? w * sst[lane] : 0.f;
            float wss = wsv;
#pragma unroll
            for (int off = 16; off > 0; off >>= 1)
                wss += __shfl_xor_sync(0xffffffffu, wss, off);
            if (lane < RSTG) wst[lane] = wsv;
            if (lane == 0) {
                float f = __expf(rm - nm);
                fsh = f;
                Zsh = Zsh * f + zst;
                Wsh = Wsh * f + wss;
                runMs = nm;
            }
        }
        __syncthreads();

        float f = fsh;
        ax *= f; ay *= f;
#pragma unroll
        for (int r = 0; r < RSTG; r++) {
            float w = wst[r];
            float2 v = *(const float2*)(tile + r * 512 + 2 * t);
            ax += w * v.x;
            ay += w * v.y;
        }
    }

    int pc = c * NCHUNK + chunk;
    *(float2*)&g_Vp[(size_t)pc * 512 + 2 * t] = make_float2(ax, ay);
    if (t == 0) { g_Mp[pc] = runMs; g_Zp[pc] = Zsh; g_Wp[pc] = Wsh; }
}

// ============================================================================
// cmat (fused reduce): y from chunk partials; craw = y.W_o + bias_o*wts;
// partial sumsq per (c, ob). grid (4, 64).
// ============================================================================
__global__ void __launch_bounds__(256) cmat_kernel(
    const float* __restrict__ W, const float* __restrict__ bias)
{
    const int ob = blockIdx.x, c = blockIdx.y;
    const int t = threadIdx.x, wid = t >> 5, lane = t & 31;
    __shared__ float ysm[512];
    __shared__ float sk[NCHUNK];
    __shared__ float ssp[8];
    __shared__ float Zs, Wts;

    if (t == 0) {
        float M = g_Mp[c * NCHUNK];
#pragma unroll
        for (int k = 1; k < NCHUNK; k++) M = fmaxf(M, g_Mp[c * NCHUNK + k]);
        float Z = 0.f, Wt = 0.f;
#pragma unroll
        for (int k = 0; k < NCHUNK; k++) {
            float e = __expf(g_Mp[c * NCHUNK + k] - M);
            sk[k] = e;
            Z  += g_Zp[c * NCHUNK + k] * e;
            Wt += g_Wp[c * NCHUNK + k] * e;
        }
        Zs = Z;
        Wts = Wt / Z;
    }
    __syncthreads();

    {
        float w0 = 0.f, w1 = 0.f;
#pragma unroll
        for (int k = 0; k < NCHUNK; k++) {
            float e = sk[k];
            float2 v = *(const float2*)&g_Vp[((size_t)(c * NCHUNK + k)) * 512 + 2 * t];
            w0 += e * v.x;
            w1 += e * v.y;
        }
        float invZ = 1.f / Zs;
        ysm[2 * t] = w0 * invZ;
        ysm[2 * t + 1] = w1 * invZ;
    }
    __syncthreads();

    const float Wts_l = Wts;
    float ss = 0.f;
#pragma unroll
    for (int i = 0; i < 16; i++) {
        int o = ob * 128 + wid * 16 + i;
        const float4* wr = (const float4*)(W + (size_t)o * 512);
        float d = 0.f;
#pragma unroll
        for (int g = 0; g < 4; g++) {
            float4 a = wr[lane + 32 * g];
            float4 b = *(const float4*)&ysm[(lane + 32 * g) * 4];
            d += a.x * b.x + a.y * b.y + a.z * b.z + a.w * b.w;
        }
#pragma unroll
        for (int off = 16; off > 0; off >>= 1)
            d += __shfl_xor_sync(0xffffffffu, d, off);
        if (lane == 0) {
            float cr = d + bias[o] * Wts_l;
            g_craw[c * 512 + o] = cr;
            ss += cr * cr;
        }
    }
    if (lane == 0) ssp[wid] = ss;
    __syncthreads();
    if (t == 0) {
        float s = 0.f;
#pragma unroll
        for (int k = 0; k < 8; k++) s += ssp[k];
        g_sqp[c * 4 + ob] = s;
    }
}

// ============================================================================
// ustep: scale from sumsq; u = scale * W^T craw ; bc = scale*(bias.craw).
// ============================================================================
__global__ void __launch_bounds__(256) ustep_kernel(
    const float* __restrict__ W, const float* __restrict__ bias)
{
    const int ob = blockIdx.x, c = blockIdx.y;
    const int t = threadIdx.x;
    const int og = t >> 6, cp = t & 63;

    __shared__ float csm[512];
    __shared__ float2 up[4][64];
    __shared__ float scsh;
    __shared__ float red2[8];

    csm[t]       = g_craw[c * 512 + t];
    csm[t + 256] = g_craw[c * 512 + t + 256];
    if (t == 0) {
        float sq = g_sqp[c * 4] + g_sqp[c * 4 + 1] + g_sqp[c * 4 + 2] + g_sqp[c * 4 + 3];
        scsh = (sq / (1.f + sq)) * rsqrtf(sq + 1e-7f);
    }
    __syncthreads();
    const float scale = scsh;

    float u0 = 0.f, u1 = 0.f;
    const float* wp = W + (size_t)(og * 128) * 512 + ob * 128 + cp * 2;
#pragma unroll 8
    for (int o = 0; o < 128; o++) {
        float co = csm[og * 128 + o];
        float2 wv = *(const float2*)(wp + (size_t)o * 512);
        u0 += co * wv.x;
        u1 += co * wv.y;
    }
    up[og][cp] = make_float2(u0, u1);
    __syncthreads();

    if (t < 64) {
        float2 a = up[0][t], b = up[1][t], d = up[2][t], e = up[3][t];
        *(float2*)&g_u[c * 512 + ob * 128 + t * 2] =
            make_float2(scale * (a.x + b.x + d.x + e.x),
                        scale * (a.y + b.y + d.y + e.y));
    }

    if (ob == 0) {
        float p = bias[t] * csm[t] + bias[t + 256] * csm[t + 256];
#pragma unroll
        for (int off = 16; off > 0; off >>= 1)
            p += __shfl_xor_sync(0xffffffffu, p, off);
        if ((t & 31) == 0) red2[t >> 5] = p;
        __syncthreads();
        if (t == 0) {
            float pp = 0.f;
#pragma unroll
            for (int k = 0; k < 8; k++) pp += red2[k];
            g_bc[c] = scale * pp;
        }
    }
}

// ============================================================================
__global__ void __launch_bounds__(256) out_kernel(float* __restrict__ out) {
    const int c = blockIdx.x, t = threadIdx.x;
    __shared__ float scsh;
    if (t == 0) {
        float sq = g_sqp[c * 4] + g_sqp[c * 4 + 1] + g_sqp[c * 4 + 2] + g_sqp[c * 4 + 3];
        scsh = (sq / (1.f + sq)) * rsqrtf(sq + 1e-7f);
    }
    __syncthreads();
    out[c * 512 + t]       = scsh * g_craw[c * 512 + t];
    out[c * 512 + t + 256] = scsh * g_craw[c * 512 + t + 256];
}

// ============================================================================
extern "C" void kernel_launch(void* const* d_in, const int* in_sizes, int n_in,
                              void* d_out, int out_size) {
    const float* x    = (const float*)d_in[0];
    const float* W    = (const float*)d_in[1];
    const float* bias = (const float*)d_in[2];
    float* out = (float*)d_out;

    void* pb = nullptr; cudaGetSymbolAddress(&pb, g_b);
    cudaMemsetAsync(pb, 0, (size_t)M_ROWS * sizeof(float));

    convw_kernel<<<256, 256>>>(W);

    static bool attr_done = false;
    if (!attr_done) {
        cudaFuncSetAttribute(gemm_norms, cudaFuncAttributeMaxDynamicSharedMemorySize, GSM_TOTAL);
        cudaFuncSetAttribute(sweep_pass, cudaFuncAttributeMaxDynamicSharedMemorySize, SWEEP_SMEM);
        attr_done = true;
    }
    gemm_norms<<<dim3(4, 1024), 256, GSM_TOTAL>>>(x, bias);

    for (int it = 0; it < 3; ++it) {
        sweep_pass<<<dim3(NCHUNK, C_CAPS), 256, SWEEP_SMEM>>>(x, it > 0 ? 1 : 0);
        cmat_kernel<<<dim3(4, C_CAPS), 256>>>(W, bias);
        if (it < 2) ustep_kernel<<<dim3(4, C_CAPS), 256>>>(W, bias);
        else        out_kernel<<<C_CAPS, 256>>>(out);
    }
}

// round 8
// speedup vs baseline: 3.0282x; 1.0776x over previous
#include <cuda_runtime.h>
#include <cuda_fp16.h>
#include <cstdint>

#define C_CAPS 64
#define S_DIM 2048
#define H_DIM 512
#define M_ROWS (C_CAPS * S_DIM)   // 131072
#define NCHUNK 16
#define CHUNK_S (S_DIM / NCHUNK)  // 128
#define RSTG 16
#define NSTG (CHUNK_S / RSTG)     // 8
#define SLOTS 3

// ---------------- device scratch ----------------
__device__ __align__(128) __half g_whf[(size_t)H_DIM * H_DIM];  // pre-swizzled fp16 W
__device__ float g_norms[4 * M_ROWS];
__device__ float g_b[M_ROWS];
__device__ float g_u[C_CAPS * H_DIM];
__device__ float g_bc[C_CAPS];
__device__ float g_Mp[C_CAPS * NCHUNK];
__device__ float g_Zp[C_CAPS * NCHUNK];
__device__ float g_Wp[C_CAPS * NCHUNK];
__device__ float g_Vp[(size_t)C_CAPS * NCHUNK * H_DIM];
__device__ float g_craw[C_CAPS * H_DIM];
__device__ float g_sqp[C_CAPS * 8];

// ---------------- helpers ----------------
__device__ __forceinline__ uint32_t smem_u32(const void* p) {
    uint32_t a;
    asm("{ .reg .u64 t; cvta.to.shared.u64 t, %1; cvt.u32.u64 %0, t; }" : "=r"(a) : "l"(p));
    return a;
}
__device__ __forceinline__ void ldsm4(uint32_t* r, uint32_t addr) {
    asm volatile("ldmatrix.sync.aligned.m8n8.x4.shared.b16 {%0,%1,%2,%3}, [%4];"
        : "=r"(r[0]), "=r"(r[1]), "=r"(r[2]), "=r"(r[3]) : "r"(addr));
}
// f16-accumulator HMMA
__device__ __forceinline__ void mma16816h(uint32_t* d, const uint32_t* a, const uint32_t* b) {
    asm volatile("mma.sync.aligned.m16n8k16.row.col.f16.f16.f16.f16 "
        "{%0,%1}, {%2,%3,%4,%5}, {%6,%7}, {%0,%1};"
        : "+r"(d[0]), "+r"(d[1])
        : "r"(a[0]), "r"(a[1]), "r"(a[2]), "r"(a[3]), "r"(b[0]), "r"(b[1]));
}
__device__ __forceinline__ void sts128(uint32_t addr, uint4 v) {
    asm volatile("st.shared.v4.b32 [%0], {%1,%2,%3,%4};"
        :: "r"(addr), "r"(v.x), "r"(v.y), "r"(v.z), "r"(v.w) : "memory");
}
#define CP_ASYNC16(dst, src) \
    asm volatile("cp.async.cg.shared.global [%0], [%1], 16;" :: "r"(dst), "l"(src) : "memory")
#define CP_COMMIT() asm volatile("cp.async.commit_group;" ::: "memory")
#define CP_WAIT(n)  asm volatile("cp.async.wait_group %0;" :: "n"(n) : "memory")

__device__ __forceinline__ uint32_t packh2(float x, float y) {
    __half2 h = __floats2half2_rn(x, y);
    return *(uint32_t*)&h;
}
__device__ __forceinline__ uint32_t tswz(uint32_t row, uint32_t kc) {
    return row * 64u + ((kc ^ ((row >> 1) & 3u)) << 4);
}

// ============================================================================
// convw: W fp32 -> pre-swizzled fp16 tiles (8KB blocks [128 rows x 32 k]).
// ============================================================================
__global__ void convw_kernel(const float* __restrict__ W) {
    int g = blockIdx.x * 256 + threadIdx.x;
    int n = g >> 7, ch = g & 127;
    int kt = ch >> 3, kc = (ch >> 1) & 3, half = ch & 1;
    int bn = n >> 7, nrow = n & 127;
    float4 v = *(const float4*)&W[(size_t)n * 512 + ch * 4];
    uint2 hi;
    hi.x = packh2(v.x, v.y);
    hi.y = packh2(v.z, v.w);
    size_t dst = ((size_t)(bn * 16 + kt) << 13) + tswz(nrow, kc) + half * 8;
    *(uint2*)((char*)g_whf + dst) = hi;
}

// ============================================================================
// GEMM (norms only): fp16 x * fp16 W, f16 accumulate. Tile 128x128, BK=32,
// 8 warps, double-buffered. B via cp.async from pre-swizzled W.
// ============================================================================
#define GSM_STAGE 16384
#define GSM_TOTAL (2 * GSM_STAGE + 512)

__device__ __forceinline__ void issueB(uint32_t stg, int bn, int kt, int t) {
    size_t tile = (size_t)(bn * 16 + kt) << 13;
    const char* sh = (const char*)g_whf + tile + t * 32;
    CP_ASYNC16(stg + 8192 + t * 32, sh);
    CP_ASYNC16(stg + 8192 + t * 32 + 16, sh + 16);
}

__global__ void __launch_bounds__(256, 2) gemm_norms(
    const float* __restrict__ x, const float* __restrict__ bias)
{
    extern __shared__ __align__(1024) char smem[];
    const uint32_t sb = smem_u32(smem);

    const int t = threadIdx.x, l = t & 31, wid = t >> 5;
    const int wm = wid & 3, wn = wid >> 2;
    const int bn = blockIdx.x, mtile = blockIdx.y;

    const int c0row = t >> 2, ckc = t & 3;
    const float* ag0 = x + ((size_t)mtile * 128 + c0row) * 512 + ckc * 8;
    const float* ag1 = x + ((size_t)mtile * 128 + c0row + 64) * 512 + ckc * 8;
    const uint32_t so0 = tswz(c0row, ckc);
    const uint32_t so1 = tswz(c0row + 64, ckc);

    uint32_t aoffA[2][2], aoffB[4][2];
#pragma unroll
    for (int mt = 0; mt < 2; mt++)
#pragma unroll
        for (int ks = 0; ks < 2; ks++) {
            uint32_t m = wm * 32 + mt * 16 + ((l >> 3) & 1) * 8 + (l & 7);
            aoffA[mt][ks] = tswz(m, ks * 2 + (l >> 4));
        }
#pragma unroll
    for (int nt2 = 0; nt2 < 4; nt2++)
#pragma unroll
        for (int ks = 0; ks < 2; ks++) {
            uint32_t n = wn * 64 + nt2 * 16 + ((l >> 4) & 1) * 8 + (l & 7);
            aoffB[nt2][ks] = tswz(n, ks * 2 + ((l >> 3) & 1));
        }

    uint32_t acc[2][8][2];
#pragma unroll
    for (int mt = 0; mt < 2; mt++)
#pragma unroll
        for (int nt = 0; nt < 8; nt++) { acc[mt][nt][0] = 0u; acc[mt][nt][1] = 0u; }

    issueB(sb, bn, 0, t);
    CP_COMMIT();
    float4 pa[2][2];
    pa[0][0] = *(const float4*)(ag0); pa[0][1] = *(const float4*)(ag0 + 4);
    pa[1][0] = *(const float4*)(ag1); pa[1][1] = *(const float4*)(ag1 + 4);

    for (int kt = 0; kt < 16; kt++) {
        const uint32_t stg = sb + (kt & 1) * GSM_STAGE;
        {
            uint4 h0, h1;
            h0.x = packh2(pa[0][0].x, pa[0][0].y); h0.y = packh2(pa[0][0].z, pa[0][0].w);
            h0.z = packh2(pa[0][1].x, pa[0][1].y); h0.w = packh2(pa[0][1].z, pa[0][1].w);
            h1.x = packh2(pa[1][0].x, pa[1][0].y); h1.y = packh2(pa[1][0].z, pa[1][0].w);
            h1.z = packh2(pa[1][1].x, pa[1][1].y); h1.w = packh2(pa[1][1].z, pa[1][1].w);
            sts128(stg + so0, h0);
            sts128(stg + so1, h1);
        }
        if (kt < 15) {
            issueB(sb + ((kt + 1) & 1) * GSM_STAGE, bn, kt + 1, t);
            CP_COMMIT();
            CP_WAIT(1);
        } else {
            CP_WAIT(0);
        }
        __syncthreads();

        if (kt < 15) {
            int ko = (kt + 1) * 32;
            pa[0][0] = *(const float4*)(ag0 + ko); pa[0][1] = *(const float4*)(ag0 + ko + 4);
            pa[1][0] = *(const float4*)(ag1 + ko); pa[1][1] = *(const float4*)(ag1 + ko + 4);
        }

#pragma unroll
        for (int ks = 0; ks < 2; ks++) {
            uint32_t ah[2][4], bh[4][4];
#pragma unroll
            for (int mt = 0; mt < 2; mt++) ldsm4(ah[mt], stg + aoffA[mt][ks]);
#pragma unroll
            for (int nt2 = 0; nt2 < 4; nt2++) ldsm4(bh[nt2], stg + 8192 + aoffB[nt2][ks]);
#pragma unroll
            for (int mt = 0; mt < 2; mt++)
#pragma unroll
                for (int nt = 0; nt < 8; nt++)
                    mma16816h(acc[mt][nt], ah[mt], &bh[nt >> 1][(nt & 1) * 2]);
        }
        __syncthreads();
    }

    float* norm_sm = (float*)(smem + 2 * GSM_STAGE);
    if (t < 128) norm_sm[t] = 0.f;
    __syncthreads();

    float2 bias2[8];
#pragma unroll
    for (int nt = 0; nt < 8; nt++)
        bias2[nt] = *(const float2*)&bias[bn * 128 + wn * 64 + nt * 8 + (l & 3) * 2];

#pragma unroll
    for (int mt = 0; mt < 2; mt++)
#pragma unroll
        for (int half = 0; half < 2; half++) {
            int r = wm * 32 + mt * 16 + (l >> 2) + half * 8;
            float ss = 0.f;
#pragma unroll
            for (int nt = 0; nt < 8; nt++) {
                float2 v = __half22float2(*(__half2*)&acc[mt][nt][half]);
                float vx = v.x + bias2[nt].x;
                float vy = v.y + bias2[nt].y;
                ss += vx * vx + vy * vy;
            }
            ss += __shfl_xor_sync(0xffffffffu, ss, 1);
            ss += __shfl_xor_sync(0xffffffffu, ss, 2);
            if ((l & 3) == 0) atomicAdd(&norm_sm[r], ss);
        }
    __syncthreads();
    if (t < 128)
        g_norms[(size_t)bn * M_ROWS + (size_t)mtile * 128 + t] = norm_sm[t];
}

// ============================================================================
// Sweep: 3-slot cp.async ring, 16-row stages (96KB dynamic smem, 2 CTAs/SM).
// ============================================================================
#define SWEEP_SMEM (SLOTS * RSTG * 512 * 4)

__device__ __forceinline__ void sweep_issue(const float* src, float* slot, int t) {
    uint32_t dst = smem_u32(slot);
#pragma unroll
    for (int i = 0; i < 8; i++) {
        int idx = t + 256 * i;
        CP_ASYNC16(dst + idx * 16, src + idx * 4);
    }
    CP_COMMIT();
}

__global__ void __launch_bounds__(256, 2) sweep_pass(const float* __restrict__ x, int do_dot) {
    extern __shared__ __align__(16) float tiles[];
    __shared__ float usm[512];
    __shared__ float bst[RSTG], sst[RSTG], wst[RSTG];
    __shared__ float runMs, Zsh, Wsh, fsh, bcs;

    const int c = blockIdx.y, chunk = blockIdx.x;
    const int t = threadIdx.x, wid = t >> 5, lane = t & 31;

    usm[t]       = do_dot ? g_u[c * 512 + t] : 0.f;
    usm[t + 256] = do_dot ? g_u[c * 512 + t + 256] : 0.f;
    if (t == 0) { runMs = -1e30f; Zsh = 0.f; Wsh = 0.f; bcs = do_dot ? g_bc[c] : 0.f; }

    const size_t rowbase = (size_t)c * S_DIM + (size_t)chunk * CHUNK_S;
    float ax = 0.f, ay = 0.f;

    sweep_issue(x + rowbase * 512, tiles, t);
    sweep_issue(x + (rowbase + RSTG) * 512, tiles + RSTG * 512, t);

    for (int st = 0; st < NSTG; st++) {
        if (st < NSTG - 1) { CP_WAIT(1); } else { CP_WAIT(0); }
        __syncthreads();
        float* tile = tiles + (st % SLOTS) * (RSTG * 512);

        if (st + 2 < NSTG)
            sweep_issue(x + (rowbase + (size_t)(st + 2) * RSTG) * 512,
                        tiles + ((st + 2) % SLOTS) * (RSTG * 512), t);

#pragma unroll
        for (int rr = 0; rr < 2; rr++) {
            int rl = wid * 2 + rr;
            float dot = 0.f;
            if (do_dot) {
                const float4* tr = (const float4*)(tile + rl * 512);
#pragma unroll
                for (int j = 0; j < 4; j++) {
                    float4 v = tr[lane + 32 * j];
                    float4 cv = *(const float4*)&usm[(lane + 32 * j) * 4];
                    dot += v.x * cv.x + v.y * cv.y + v.z * cv.z + v.w * cv.w;
                }
#pragma unroll
                for (int off = 16; off > 0; off >>= 1)
                    dot += __shfl_xor_sync(0xffffffffu, dot, off);
            }
            if (lane == 0) {
                size_t row = rowbase + st * RSTG + rl;
                float sq = g_norms[row] + g_norms[M_ROWS + row]
                         + g_norms[2 * M_ROWS + row] + g_norms[3 * M_ROWS + row];
                float scale = (sq / (1.f + sq)) * rsqrtf(sq + 1e-7f);
                float bv;
                if (do_dot) {
                    bv = g_b[row] + scale * (dot + bcs);
                    g_b[row] = bv;
                } else {
                    bv = 0.f;
                }
                bst[rl] = bv;
                sst[rl] = scale;
            }
        }
        __syncthreads();

        if (t < 32) {
            float v = (lane < RSTG) ? bst[lane] : -1e30f;
            float m = v;
#pragma unroll
            for (int off = 16; off > 0; off >>= 1)
                m = fmaxf(m, __shfl_xor_sync(0xffffffffu, m, off));
            float rm = runMs;
            float nm = fmaxf(rm, m);
            float w = __expf(v - nm);
            float zst = w;
#pragma unroll
            for (int off = 16; off > 0; off >>= 1)
                zst += __shfl_xor_sync(0xffffffffu, zst, off);
            float wsv = (lane < RSTG) ? w * sst[lane] : 0.f;
            float wss = wsv;
#pragma unroll
            for (int off = 16; off > 0; off >>= 1)
                wss += __shfl_xor_sync(0xffffffffu, wss, off);
            if (lane < RSTG) wst[lane] = wsv;
            if (lane == 0) {
                float f = __expf(rm - nm);
                fsh = f;
                Zsh = Zsh * f + zst;
                Wsh = Wsh * f + wss;
                runMs = nm;
            }
        }
        __syncthreads();

        float f = fsh;
        ax *= f; ay *= f;
#pragma unroll
        for (int r = 0; r < RSTG; r++) {
            float w = wst[r];
            float2 v = *(const float2*)(tile + r * 512 + 2 * t);
            ax += w * v.x;
            ay += w * v.y;
        }
    }

    int pc = c * NCHUNK + chunk;
    *(float2*)&g_Vp[(size_t)pc * 512 + 2 * t] = make_float2(ax, ay);
    if (t == 0) { g_Mp[pc] = runMs; g_Zp[pc] = Zsh; g_Wp[pc] = Wsh; }
}

// ============================================================================
// cmat (fused reduce): y from chunk partials; craw = y.W_o + bias_o*wts;
// partial sumsq per (c, ob). grid (8, 64): 64 outputs per block, warp per 8.
// ============================================================================
__global__ void __launch_bounds__(256) cmat_kernel(
    const float* __restrict__ W, const float* __restrict__ bias)
{
    const int ob = blockIdx.x, c = blockIdx.y;
    const int t = threadIdx.x, wid = t >> 5, lane = t & 31;
    __shared__ float ysm[512];
    __shared__ float sk[NCHUNK];
    __shared__ float ssp[8];
    __shared__ float Zs, Wts;

    if (t == 0) {
        float M = g_Mp[c * NCHUNK];
#pragma unroll
        for (int k = 1; k < NCHUNK; k++) M = fmaxf(M, g_Mp[c * NCHUNK + k]);
        float Z = 0.f, Wt = 0.f;
#pragma unroll
        for (int k = 0; k < NCHUNK; k++) {
            float e = __expf(g_Mp[c * NCHUNK + k] - M);
            sk[k] = e;
            Z  += g_Zp[c * NCHUNK + k] * e;
            Wt += g_Wp[c * NCHUNK + k] * e;
        }
        Zs = Z;
        Wts = Wt / Z;
    }
    __syncthreads();

    {
        float w0 = 0.f, w1 = 0.f;
#pragma unroll
        for (int k = 0; k < NCHUNK; k++) {
            float e = sk[k];
            float2 v = *(const float2*)&g_Vp[((size_t)(c * NCHUNK + k)) * 512 + 2 * t];
            w0 += e * v.x;
            w1 += e * v.y;
        }
        float invZ = 1.f / Zs;
        ysm[2 * t] = w0 * invZ;
        ysm[2 * t + 1] = w1 * invZ;
    }
    __syncthreads();

    const float Wts_l = Wts;
    float ss = 0.f;
#pragma unroll
    for (int i = 0; i < 8; i++) {
        int o = ob * 64 + wid * 8 + i;
        const float4* wr = (const float4*)(W + (size_t)o * 512);
        float d = 0.f;
#pragma unroll
        for (int g = 0; g < 4; g++) {
            float4 a = wr[lane + 32 * g];
            float4 b = *(const float4*)&ysm[(lane + 32 * g) * 4];
            d += a.x * b.x + a.y * b.y + a.z * b.z + a.w * b.w;
        }
#pragma unroll
        for (int off = 16; off > 0; off >>= 1)
            d += __shfl_xor_sync(0xffffffffu, d, off);
        if (lane == 0) {
            float cr = d + bias[o] * Wts_l;
            g_craw[c * 512 + o] = cr;
            ss += cr * cr;
        }
    }
    if (lane == 0) ssp[wid] = ss;
    __syncthreads();
    if (t == 0) {
        float s = 0.f;
#pragma unroll
        for (int k = 0; k < 8; k++) s += ssp[k];
        g_sqp[c * 8 + ob] = s;
    }
}

// ============================================================================
// ustep: scale; u = scale * W^T craw ; bc = scale*(bias.craw).
// grid (8, 64): 64 h-columns per block; o-loop split 8 ways (64 each).
// ============================================================================
__global__ void __launch_bounds__(256) ustep_kernel(
    const float* __restrict__ W, const float* __restrict__ bias)
{
    const int ob = blockIdx.x, c = blockIdx.y;
    const int t = threadIdx.x;
    const int og = t >> 5, cp = t & 31;

    __shared__ float csm[512];
    __shared__ float2 up[8][32];
    __shared__ float scsh;
    __shared__ float red2[8];

    csm[t]       = g_craw[c * 512 + t];
    csm[t + 256] = g_craw[c * 512 + t + 256];
    if (t == 0) {
        float sq = 0.f;
#pragma unroll
        for (int k = 0; k < 8; k++) sq += g_sqp[c * 8 + k];
        scsh = (sq / (1.f + sq)) * rsqrtf(sq + 1e-7f);
    }
    __syncthreads();
    const float scale = scsh;

    float u0 = 0.f, u1 = 0.f;
    const float* wp = W + (size_t)(og * 64) * 512 + ob * 64 + cp * 2;
#pragma unroll 8
    for (int o = 0; o < 64; o++) {
        float co = csm[og * 64 + o];
        float2 wv = *(const float2*)(wp + (size_t)o * 512);
        u0 += co * wv.x;
        u1 += co * wv.y;
    }
    up[og][cp] = make_float2(u0, u1);
    __syncthreads();

    if (t < 32) {
        float sx = 0.f, sy = 0.f;
#pragma unroll
        for (int k = 0; k < 8; k++) { sx += up[k][t].x; sy += up[k][t].y; }
        *(float2*)&g_u[c * 512 + ob * 64 + t * 2] =
            make_float2(scale * sx, scale * sy);
    }

    if (ob == 0) {
        float p = bias[t] * csm[t] + bias[t + 256] * csm[t + 256];
#pragma unroll
        for (int off = 16; off > 0; off >>= 1)
            p += __shfl_xor_sync(0xffffffffu, p, off);
        if ((t & 31) == 0) red2[t >> 5] = p;
        __syncthreads();
        if (t == 0) {
            float pp = 0.f;
#pragma unroll
            for (int k = 0; k < 8; k++) pp += red2[k];
            g_bc[c] = scale * pp;
        }
    }
}

// ============================================================================
__global__ void __launch_bounds__(256) out_kernel(float* __restrict__ out) {
    const int c = blockIdx.x, t = threadIdx.x;
    __shared__ float scsh;
    if (t == 0) {
        float sq = 0.f;
#pragma unroll
        for (int k = 0; k < 8; k++) sq += g_sqp[c * 8 + k];
        scsh = (sq / (1.f + sq)) * rsqrtf(sq + 1e-7f);
    }
    __syncthreads();
    out[c * 512 + t]       = scsh * g_craw[c * 512 + t];
    out[c * 512 + t + 256] = scsh * g_craw[c * 512 + t + 256];
}

// ============================================================================
extern "C" void kernel_launch(void* const* d_in, const int* in_sizes, int n_in,
                              void* d_out, int out_size) {
    const float* x    = (const float*)d_in[0];
    const float* W    = (const float*)d_in[1];
    const float* bias = (const float*)d_in[2];
    float* out = (float*)d_out;

    void* pb = nullptr; cudaGetSymbolAddress(&pb, g_b);
    cudaMemsetAsync(pb, 0, (size_t)M_ROWS * sizeof(float));

    convw_kernel<<<256, 256>>>(W);

    static bool attr_done = false;
    if (!attr_done) {
        cudaFuncSetAttribute(gemm_norms, cudaFuncAttributeMaxDynamicSharedMemorySize, GSM_TOTAL);
        cudaFuncSetAttribute(sweep_pass, cudaFuncAttributeMaxDynamicSharedMemorySize, SWEEP_SMEM);
        attr_done = true;
    }
    gemm_norms<<<dim3(4, 1024), 256, GSM_TOTAL>>>(x, bias);

    for (int it = 0; it < 3; ++it) {
        sweep_pass<<<dim3(NCHUNK, C_CAPS), 256, SWEEP_SMEM>>>(x, it > 0 ? 1 : 0);
        cmat_kernel<<<dim3(8, C_CAPS), 256>>>(W, bias);
        if (it < 2) ustep_kernel<<<dim3(8, C_CAPS), 256>>>(W, bias);
        else        out_kernel<<<C_CAPS, 256>>>(out);
    }
}